// round 13
// baseline (speedup 1.0000x reference)
#include <cuda_runtime.h>
#include <cuda_fp16.h>
#include <math.h>
#include <stdint.h>

#define BATCH 32768
#define FDIM 512
#define HS 256
#define OUTD 128
#define STEPS 5
#define EPSBN 1e-5f

typedef __half fp16;

// ---------------- scratch (device globals; no allocation) ----------------
__device__ fp16  g_featsh[BATCH * FDIM];
__device__ fp16  g_A[BATCH * FDIM];
__device__ fp16  g_h0[BATCH * HS];
__device__ fp16  g_h1[BATCH * HS];
__device__ float g_prior[BATCH * FDIM];
__device__ float g_acc[BATCH * OUTD];

// prepped weights ([N,K] fp16; GLU ones N-permuted with 8-col a/b interleave)
__device__ fp16 g_W0[512 * 512];
__device__ fp16 g_W1[512 * 256];
__device__ fp16 g_WU[12 * 512 * 256];
__device__ fp16 g_WA[5 * 512 * 128];
__device__ float g_fts[6 * 4 * 512], g_ftt[6 * 4 * 512];
__device__ float g_as[5 * 512], g_at[5 * 512];

// ---------------- PTX helpers ----------------
__device__ __forceinline__ uint32_t smem_u32(const void* p) {
    uint32_t a;
    asm("{ .reg .u64 t; cvta.to.shared.u64 t, %1; cvt.u32.u64 %0, t; }" : "=r"(a) : "l"(p));
    return a;
}
__device__ __forceinline__ void cpa16(uint32_t s, const void* g) {
    asm volatile("cp.async.cg.shared.global [%0], [%1], 16;" :: "r"(s), "l"(g));
}
__device__ __forceinline__ void cpa_commit() {
    asm volatile("cp.async.commit_group;" ::: "memory");
}
template<int N>
__device__ __forceinline__ void cpa_wait() {
    asm volatile("cp.async.wait_group %0;" :: "n"(N) : "memory");
}
__device__ __forceinline__ void ldm4(uint32_t* v, uint32_t addr) {
    asm volatile("ldmatrix.sync.aligned.m8n8.x4.shared.b16 {%0,%1,%2,%3}, [%4];"
                 : "=r"(v[0]), "=r"(v[1]), "=r"(v[2]), "=r"(v[3]) : "r"(addr));
}
__device__ __forceinline__ void mma16(float* c, const uint32_t* a, uint32_t b0, uint32_t b1) {
    asm("mma.sync.aligned.m16n8k16.row.col.f32.f16.f16.f32 "
        "{%0,%1,%2,%3}, {%4,%5,%6,%7}, {%8,%9}, {%0,%1,%2,%3};"
        : "+f"(c[0]), "+f"(c[1]), "+f"(c[2]), "+f"(c[3])
        : "r"(a[0]), "r"(a[1]), "r"(a[2]), "r"(a[3]), "r"(b0), "r"(b1));
}

// ---------------- prep ----------------
__device__ __forceinline__ void prep_one(const float* W, int K, int idx, fp16* o)
{
    int n = idx / K, k = idx - n * K;
    int q = n >> 4, rr = n & 15, half = rr >> 3, jl = rr & 7;
    int col = (half ? 256 : 0) + q * 8 + jl;
    o[idx] = __float2half_rn(W[(size_t)k * 512 + col]);
}

__global__ void k_prep_glu_all(const float* __restrict__ Ws0,
                               const float* __restrict__ Ws1,
                               const float* __restrict__ Wu)
{
    int idx = blockIdx.x * 256 + threadIdx.x;
    const int N0 = 512 * 512;
    const int N1 = N0 + 512 * 256;
    const int N2 = N1 + 12 * 512 * 256;
    if (idx < N0) {
        prep_one(Ws0, 512, idx, g_W0);
    } else if (idx < N1) {
        prep_one(Ws1, 256, idx - N0, g_W1);
    } else if (idx < N2) {
        int r = idx - N1;
        int mi = r / (512 * 256);
        int li = r - mi * (512 * 256);
        prep_one(Wu + (size_t)mi * 256 * 512, 256, li, g_WU + (size_t)mi * 512 * 256);
    }
}

__global__ void k_prep_att_bn(const float* __restrict__ Wa,
                              const float* __restrict__ fg, const float* __restrict__ fb,
                              const float* __restrict__ fm, const float* __restrict__ fv,
                              const float* __restrict__ ag, const float* __restrict__ ab,
                              const float* __restrict__ am, const float* __restrict__ av)
{
    int idx = blockIdx.x * 256 + threadIdx.x;
    if (idx < 5 * 512 * 128) {
        int s = idx / (512 * 128);
        int r = idx - s * 512 * 128;
        int n = r >> 7, k = r & 127;
        g_WA[idx] = __float2half_rn(Wa[(size_t)s * 128 * 512 + (size_t)k * 512 + n]);
    }
    if (idx < 6 * 4 * 512) {
        float s = fg[idx] * rsqrtf(fv[idx] + EPSBN);
        g_fts[idx] = s;
        g_ftt[idx] = fb[idx] - fm[idx] * s;
    }
    if (idx < 5 * 512) {
        float s = ag[idx] * rsqrtf(av[idx] + EPSBN);
        g_as[idx] = s;
        g_at[idx] = ab[idx] - am[idx] * s;
    }
}

__global__ void k_init(const float* __restrict__ feat,
                       const float* __restrict__ g, const float* __restrict__ b,
                       const float* __restrict__ m, const float* __restrict__ v)
{
    int i = blockIdx.x * blockDim.x + threadIdx.x;
    if (i < BATCH * FDIM) {
        int c = i & (FDIM - 1);
        float f = g[c] * (feat[i] - m[c]) * rsqrtf(v[c] + EPSBN) + b[c];
        fp16 h = __float2half_rn(f);
        g_featsh[i] = h;
        g_A[i] = h;
        g_prior[i] = 1.0f;
        if (i < BATCH * OUTD) g_acc[i] = 0.0f;
    }
}

// ---------------- GLU HMMA GEMM (unchanged R12 winner) ----------------
// 256 threads, 3 CTAs/SM. BM=64, BN=128, BK=64. Warp grid 2(M)x4(N), warp tile 32x32.
#define STAGE_BYTES 24576     // A 8K | B 16K
#define NSTAGE 3
#define PARAM_OFF   (NSTAGE * STAGE_BYTES)
#define SMEM_TOTAL  (PARAM_OFF + 1024)

__global__ __launch_bounds__(256, 3)
void k_mma(const fp16* __restrict__ A, int lda, int K,
           const fp16* __restrict__ B,
           const float* __restrict__ bs, const float* __restrict__ bt,
           const fp16* __restrict__ resh,
           fp16* __restrict__ outh,
           float* __restrict__ accp)
{
    extern __shared__ __align__(128) char smem[];
    const int tid = threadIdx.x, wid = tid >> 5, lid = tid & 31;
    const int wm = wid >> 2, wn = wid & 3;
    const int g = blockIdx.x;
    const int row0 = blockIdx.y * 64;
    const uint32_t sb = smem_u32(smem);

    if (tid < 128) {
        float* sE = (float*)(smem + PARAM_OFF);
        float* tE = (float*)(smem + PARAM_OFF + 512);
        int q2 = tid >> 4, rr = tid & 15, half = rr >> 3, jl = rr & 7;
        int col = (half ? 256 : 0) + g * 64 + q2 * 8 + jl;
        sE[tid] = bs[col];
        tE[tid] = bt[col];
    }

    float acc[8][4];
#pragma unroll
    for (int i = 0; i < 8; i++)
#pragma unroll
        for (int j = 0; j < 4; j++) acc[i][j] = 0.0f;

    const int nch = K >> 6;

    const char* gA[2];
    const char* gB[4];
    uint32_t soA[2], soB[4];
#pragma unroll
    for (int i = 0; i < 2; i++) {
        int idx = tid + i * 256;
        int r = idx >> 3, c = idx & 7;
        soA[i] = (uint32_t)(r * 128 + ((c ^ (r & 7)) << 4));
        gA[i] = (const char*)(A + (size_t)(row0 + r) * lda + c * 8);
    }
#pragma unroll
    for (int i = 0; i < 4; i++) {
        int idx = tid + i * 256;
        int r = idx >> 3, c = idx & 7;
        soB[i] = (uint32_t)(8192 + r * 128 + ((c ^ (r & 7)) << 4));
        gB[i] = (const char*)(B + (size_t)(g * 128 + r) * K + c * 8);
    }

    auto load_stage = [&](int ch) {
        const uint32_t st = sb + (ch % NSTAGE) * STAGE_BYTES;
        const int kb = ch << 7;
#pragma unroll
        for (int i = 0; i < 2; i++) cpa16(st + soA[i], gA[i] + kb);
#pragma unroll
        for (int i = 0; i < 4; i++) cpa16(st + soB[i], gB[i] + kb);
    };

#pragma unroll
    for (int p = 0; p < 2; p++) {
        if (p < nch) load_stage(p);
        cpa_commit();
    }

    const int lr = lid & 15, lc = lid >> 4;
    uint32_t offA[2], offB2[2];
#pragma unroll
    for (int m = 0; m < 2; m++) {
        int r = wm * 32 + m * 16 + lr;
        offA[m] = (uint32_t)(r * 128 + ((lc ^ (r & 7)) << 4));
    }
#pragma unroll
    for (int q = 0; q < 2; q++) {
        int r = wn * 32 + q * 16 + lr;
        offB2[q] = (uint32_t)(8192 + r * 128 + ((lc ^ (r & 7)) << 4));
    }

    for (int ch = 0; ch < nch; ch++) {
        cpa_wait<1>();
        __syncthreads();
        if (ch + 2 < nch) load_stage(ch + 2);
        cpa_commit();

        const uint32_t st = sb + (ch % NSTAGE) * STAGE_BYTES;
        uint32_t aH0 = st + offA[0], aH1 = st + offA[1];
        uint32_t aB0 = st + offB2[0], aB1 = st + offB2[1];

#pragma unroll
        for (int ks = 0; ks < 4; ks++) {
            uint32_t ah[2][4], bq[2][4];
            ldm4(ah[0], aH0); ldm4(ah[1], aH1);
            ldm4(bq[0], aB0); ldm4(bq[1], aB1);
#pragma unroll
            for (int m = 0; m < 2; m++) {
                mma16(acc[m * 4 + 0], ah[m], bq[0][0], bq[0][2]);
                mma16(acc[m * 4 + 1], ah[m], bq[0][1], bq[0][3]);
                mma16(acc[m * 4 + 2], ah[m], bq[1][0], bq[1][2]);
                mma16(acc[m * 4 + 3], ah[m], bq[1][1], bq[1][3]);
            }
            const uint32_t d = (ks & 1) ? 96u : 32u;
            aH0 ^= d; aH1 ^= d;
            aB0 ^= d; aB1 ^= d;
        }
    }

    const float* sE = (const float*)(smem + PARAM_OFF);
    const float* tE = (const float*)(smem + PARAM_OFF + 512);
    const int gid = lid >> 2, tp = lid & 3;

#pragma unroll
    for (int m = 0; m < 2; m++) {
#pragma unroll
        for (int t = 0; t < 2; t++) {
            const int ja = wn * 32 + t * 16 + tp * 2;
            const int jb = ja + 8;
            const int cn = g * 64 + (wn * 2 + t) * 8 + tp * 2;
            const float sa0 = sE[ja], sa1 = sE[ja + 1];
            const float ta0 = tE[ja], ta1 = tE[ja + 1];
            const float sb0 = sE[jb], sb1 = sE[jb + 1];
            const float tb0 = tE[jb], tb1 = tE[jb + 1];
            const float* ca = acc[m * 4 + 2 * t];
            const float* cb = acc[m * 4 + 2 * t + 1];
#pragma unroll
            for (int h = 0; h < 2; h++) {
                const int row = row0 + wm * 32 + m * 16 + gid + h * 8;
                float xa0 = ca[2 * h] * sa0 + ta0;
                float xa1 = ca[2 * h + 1] * sa1 + ta1;
                float xb0 = cb[2 * h] * sb0 + tb0;
                float xb1 = cb[2 * h + 1] * sb1 + tb1;
                float o0 = xa0 * (1.0f / (1.0f + __expf(-xb0)));
                float o1 = xa1 * (1.0f / (1.0f + __expf(-xb1)));
                const size_t ob = (size_t)row * HS + cn;
                if (resh) {
                    __half2 rh = *(const __half2*)(resh + ob);
                    o0 = fmaf(__half2float(rh.x), 0.70710678118654752f, o0);
                    o1 = fmaf(__half2float(rh.y), 0.70710678118654752f, o1);
                }
                __half2 hh;
                hh.x = __float2half_rn(o0);
                hh.y = __float2half_rn(o1);
                *(__half2*)(outh + ob) = hh;
                if (accp && g < 2) {
                    float2* ap = (float2*)(accp + (size_t)row * OUTD + cn);
                    float2 av = *ap;
                    av.x += fmaxf(o0, 0.0f);
                    av.y += fmaxf(o1, 0.0f);
                    *ap = av;
                }
            }
        }
    }
}

// ---------------- fused attention GEMM + sparsemax ----------------
// BM=64, BN=512 (full row), K=128, 512 threads, warp grid 2(M)x8(N), tile 32x64.
// z kept in smem fp32 (reuses stage region); per-warp bisection sparsemax.
#define ATT_STAGE 73728                    // A 8K | B 64K
#define ATT_PARAM (2 * ATT_STAGE)          // 147456
#define ATT_SMEM  (ATT_PARAM + 4096)       // 151552

__global__ __launch_bounds__(512, 1)
void k_att(const fp16* __restrict__ A, int lda,
           const fp16* __restrict__ B,
           const float* __restrict__ bs, const float* __restrict__ bt,
           float* __restrict__ prior,
           float* __restrict__ maskOut, fp16* __restrict__ mf)
{
    extern __shared__ __align__(128) char smem[];
    const int tid = threadIdx.x, wid = tid >> 5, lid = tid & 31;
    const int wm = wid >> 3, wn = wid & 7;
    const int row0 = blockIdx.x * 64;
    const uint32_t sb = smem_u32(smem);
    float* zsm = (float*)smem;             // 64x512 fp32, overlays stages post-GEMM

    {
        float* sE = (float*)(smem + ATT_PARAM);
        float* tE = (float*)(smem + ATT_PARAM + 2048);
        sE[tid] = bs[tid];
        tE[tid] = bt[tid];
    }

    float acc[16][4];
#pragma unroll
    for (int i = 0; i < 16; i++)
#pragma unroll
        for (int j = 0; j < 4; j++) acc[i][j] = 0.0f;

    // loads: A 1 piece/thread (64 rows), B 8 pieces/thread (512 rows)
    uint32_t soA0;
    const char* gA0;
    {
        int r = tid >> 3, c = tid & 7;
        soA0 = (uint32_t)(r * 128 + ((c ^ (r & 7)) << 4));
        gA0 = (const char*)(A + (size_t)(row0 + r) * lda + c * 8);
    }
    const char* gB[8];
    uint32_t soB[8];
#pragma unroll
    for (int i = 0; i < 8; i++) {
        int idx = tid + i * 512;
        int r = idx >> 3, c = idx & 7;
        soB[i] = (uint32_t)(8192 + r * 128 + ((c ^ (r & 7)) << 4));
        gB[i] = (const char*)(B + (size_t)r * 128 + c * 8);
    }

#pragma unroll
    for (int ch = 0; ch < 2; ch++) {
        const uint32_t st = sb + ch * ATT_STAGE;
        const int kb = ch << 7;
        cpa16(st + soA0, gA0 + kb);
#pragma unroll
        for (int i = 0; i < 8; i++) cpa16(st + soB[i], gB[i] + kb);
        cpa_commit();
    }

    const int lr = lid & 15, lc = lid >> 4;
    uint32_t offA[2], offB4[4];
#pragma unroll
    for (int m = 0; m < 2; m++) {
        int r = wm * 32 + m * 16 + lr;
        offA[m] = (uint32_t)(r * 128 + ((lc ^ (r & 7)) << 4));
    }
#pragma unroll
    for (int nb = 0; nb < 4; nb++) {
        int r = wn * 64 + nb * 16 + lr;
        offB4[nb] = (uint32_t)(8192 + r * 128 + ((lc ^ (r & 7)) << 4));
    }

#pragma unroll
    for (int ch = 0; ch < 2; ch++) {
        if (ch == 0) cpa_wait<1>(); else cpa_wait<0>();
        __syncthreads();
        const uint32_t st = sb + ch * ATT_STAGE;
        uint32_t aH0 = st + offA[0], aH1 = st + offA[1];
        uint32_t aB0 = st + offB4[0], aB1 = st + offB4[1];
        uint32_t aB2 = st + offB4[2], aB3 = st + offB4[3];
#pragma unroll
        for (int ks = 0; ks < 4; ks++) {
            uint32_t ah[2][4], bq[4][4];
            ldm4(ah[0], aH0); ldm4(ah[1], aH1);
            ldm4(bq[0], aB0); ldm4(bq[1], aB1);
            ldm4(bq[2], aB2); ldm4(bq[3], aB3);
#pragma unroll
            for (int nb = 0; nb < 4; nb++)
#pragma unroll
                for (int m = 0; m < 2; m++) {
                    mma16(acc[m * 8 + 2 * nb],     ah[m], bq[nb][0], bq[nb][2]);
                    mma16(acc[m * 8 + 2 * nb + 1], ah[m], bq[nb][1], bq[nb][3]);
                }
            const uint32_t d = (ks & 1) ? 96u : 32u;
            aH0 ^= d; aH1 ^= d;
            aB0 ^= d; aB1 ^= d; aB2 ^= d; aB3 ^= d;
        }
    }
    __syncthreads();   // all warps done reading stages -> safe to overlay z

    // write z = (acc*s + t) * prior  into smem fp32
    {
        const float* sE = (const float*)(smem + ATT_PARAM);
        const float* tE = (const float*)(smem + ATT_PARAM + 2048);
        const int gid = lid >> 2, tp = lid & 3;
#pragma unroll
        for (int m = 0; m < 2; m++) {
#pragma unroll
            for (int nb2 = 0; nb2 < 8; nb2++) {
                const int cn = wn * 64 + nb2 * 8 + tp * 2;
                const float s0 = sE[cn], s1 = sE[cn + 1];
                const float t0 = tE[cn], t1 = tE[cn + 1];
                const float* ca = acc[m * 8 + nb2];
#pragma unroll
                for (int h = 0; h < 2; h++) {
                    const int row = wm * 32 + m * 16 + gid + h * 8;
                    const size_t gidx = (size_t)(row0 + row) * FDIM + cn;
                    float2 pr = *(const float2*)(prior + gidx);
                    float2 zz;
                    zz.x = (ca[2 * h] * s0 + t0) * pr.x;
                    zz.y = (ca[2 * h + 1] * s1 + t1) * pr.y;
                    *(float2*)(zsm + row * 512 + cn) = zz;
                }
            }
        }
    }
    __syncthreads();

    // sparsemax: each warp handles 4 rows from smem
#pragma unroll 1
    for (int rr = 0; rr < 4; rr++) {
        const int row = wid * 4 + rr;
        const int grow = row0 + row;
        const size_t base = (size_t)grow * 512;
        float v[16];
#pragma unroll
        for (int q = 0; q < 4; q++) {
            float4 t = *(const float4*)(zsm + row * 512 + q * 128 + lid * 4);
            v[q * 4 + 0] = t.x; v[q * 4 + 1] = t.y; v[q * 4 + 2] = t.z; v[q * 4 + 3] = t.w;
        }
        float zmax = v[0];
#pragma unroll
        for (int i = 1; i < 16; i++) zmax = fmaxf(zmax, v[i]);
#pragma unroll
        for (int o = 16; o; o >>= 1) zmax = fmaxf(zmax, __shfl_xor_sync(0xffffffffu, zmax, o));

        float lo = zmax - 1.0f, hi = zmax;
        for (int it = 0; it < 20; it++) {
            float mid = 0.5f * (lo + hi);
            float s = 0.0f;
#pragma unroll
            for (int i = 0; i < 16; i++) s += fmaxf(v[i] - mid, 0.0f);
#pragma unroll
            for (int o = 16; o; o >>= 1) s += __shfl_xor_sync(0xffffffffu, s, o);
            if (s >= 1.0f) lo = mid; else hi = mid;
        }
        float sum = 0.0f, cnt = 0.0f;
#pragma unroll
        for (int i = 0; i < 16; i++) {
            if (v[i] > lo) { sum += v[i]; cnt += 1.0f; }
        }
#pragma unroll
        for (int o = 16; o; o >>= 1) {
            sum += __shfl_xor_sync(0xffffffffu, sum, o);
            cnt += __shfl_xor_sync(0xffffffffu, cnt, o);
        }
        const float tau = (sum - 1.0f) / cnt;

#pragma unroll
        for (int q = 0; q < 4; q++) {
            const size_t off = base + q * 128 + lid * 4;
            float4 mk;
            mk.x = fmaxf(v[q * 4 + 0] - tau, 0.0f);
            mk.y = fmaxf(v[q * 4 + 1] - tau, 0.0f);
            mk.z = fmaxf(v[q * 4 + 2] - tau, 0.0f);
            mk.w = fmaxf(v[q * 4 + 3] - tau, 0.0f);
            *(float4*)(maskOut + off) = mk;
            float4 pr = *(const float4*)(prior + off);
            pr.x *= (1.5f - mk.x); pr.y *= (1.5f - mk.y);
            pr.z *= (1.5f - mk.z); pr.w *= (1.5f - mk.w);
            *(float4*)(prior + off) = pr;
            __half2 f01 = *(const __half2*)(g_featsh + off);
            __half2 f23 = *(const __half2*)(g_featsh + off + 2);
            __half2 p0, p1;
            p0.x = __float2half_rn(mk.x * __half2float(f01.x));
            p0.y = __float2half_rn(mk.y * __half2float(f01.y));
            p1.x = __float2half_rn(mk.z * __half2float(f23.x));
            p1.y = __float2half_rn(mk.w * __half2float(f23.y));
            *(__half2*)(mf + off) = p0;
            *(__half2*)(mf + off + 2) = p1;
        }
    }
}

// ---------------- final projection ----------------
__global__ __launch_bounds__(256)
void k_fin(const float* __restrict__ A, const float* __restrict__ W,
           const float* __restrict__ bias, float* __restrict__ C)
{
    __shared__ float As[16][128];
    __shared__ float Ws[16][64];
    const int tid = threadIdx.x;
    const int ty = tid >> 4, tx = tid & 15;
    const int row0 = blockIdx.y * 128;
    const int col0 = blockIdx.x * 64;

    float acc[8][4];
#pragma unroll
    for (int r = 0; r < 8; r++)
#pragma unroll
        for (int c = 0; c < 4; c++) acc[r][c] = 0.f;

    for (int kt = 0; kt < 128; kt += 16) {
#pragma unroll
        for (int l = 0; l < 2; l++) {
            int li = tid * 2 + l;
            int r = li >> 2, kq = (li & 3) * 4;
            float4 av = *(const float4*)(A + (size_t)(row0 + r) * 128 + kt + kq);
            As[kq + 0][r] = av.x; As[kq + 1][r] = av.y;
            As[kq + 2][r] = av.z; As[kq + 3][r] = av.w;
        }
        *(float4*)&Ws[tid >> 4][(tid & 15) * 4] =
            *(const float4*)(W + (size_t)(kt + (tid >> 4)) * 128 + col0 + (tid & 15) * 4);
        __syncthreads();
#pragma unroll
        for (int kk = 0; kk < 16; kk++) {
            float a[8];
            float4 a0 = *(float4*)&As[kk][ty * 8];
            float4 a1 = *(float4*)&As[kk][ty * 8 + 4];
            a[0] = a0.x; a[1] = a0.y; a[2] = a0.z; a[3] = a0.w;
            a[4] = a1.x; a[5] = a1.y; a[6] = a1.z; a[7] = a1.w;
            float4 w0 = *(float4*)&Ws[kk][tx * 4];
            float wv[4] = {w0.x, w0.y, w0.z, w0.w};
#pragma unroll
            for (int r = 0; r < 8; r++)
#pragma unroll
                for (int c = 0; c < 4; c++) acc[r][c] += a[r] * wv[c];
        }
        __syncthreads();
    }
#pragma unroll
    for (int r = 0; r < 8; r++) {
        int gr = row0 + ty * 8 + r;
#pragma unroll
        for (int c = 0; c < 4; c++) {
            int gc = col0 + tx * 4 + c;
            C[(size_t)gr * 128 + gc] = acc[r][c] + bias[gc];
        }
    }
}

// ---------------- launch ----------------
extern "C" void kernel_launch(void* const* d_in, const int* in_sizes, int n_in,
                              void* d_out, int out_size)
{
    const float* features = (const float*)d_in[0];
    const float* bn0_g = (const float*)d_in[1];
    const float* bn0_b = (const float*)d_in[2];
    const float* bn0_m = (const float*)d_in[3];
    const float* bn0_v = (const float*)d_in[4];
    const float* Ws0   = (const float*)d_in[5];
    const float* Ws1   = (const float*)d_in[6];
    const float* Wu    = (const float*)d_in[7];
    const float* ft_g  = (const float*)d_in[8];
    const float* ft_b  = (const float*)d_in[9];
    const float* ft_m  = (const float*)d_in[10];
    const float* ft_v  = (const float*)d_in[11];
    const float* W_att = (const float*)d_in[12];
    const float* att_g = (const float*)d_in[13];
    const float* att_b = (const float*)d_in[14];
    const float* att_m = (const float*)d_in[15];
    const float* att_v = (const float*)d_in[16];
    const float* Wf    = (const float*)d_in[17];
    const float* bf    = (const float*)d_in[18];

    float *prior, *acc;
    fp16 *A, *h0, *h1;
    fp16 *W0, *W1, *WU, *WA;
    float *fts, *ftt, *as, *at;
    cudaGetSymbolAddress((void**)&A, g_A);
    cudaGetSymbolAddress((void**)&h0, g_h0);
    cudaGetSymbolAddress((void**)&h1, g_h1);
    cudaGetSymbolAddress((void**)&prior, g_prior);
    cudaGetSymbolAddress((void**)&acc, g_acc);
    cudaGetSymbolAddress((void**)&W0, g_W0);
    cudaGetSymbolAddress((void**)&W1, g_W1);
    cudaGetSymbolAddress((void**)&WU, g_WU);
    cudaGetSymbolAddress((void**)&WA, g_WA);
    cudaGetSymbolAddress((void**)&fts, g_fts);
    cudaGetSymbolAddress((void**)&ftt, g_ftt);
    cudaGetSymbolAddress((void**)&as, g_as);
    cudaGetSymbolAddress((void**)&at, g_at);

    float* outF  = (float*)d_out;
    float* masks = outF + (size_t)BATCH * OUTD;

    static bool attr_set = false;
    if (!attr_set) {
        cudaFuncSetAttribute(k_mma, cudaFuncAttributeMaxDynamicSharedMemorySize, SMEM_TOTAL);
        cudaFuncSetAttribute(k_att, cudaFuncAttributeMaxDynamicSharedMemorySize, ATT_SMEM);
        attr_set = true;
    }

    const int PREP_N = 512 * 512 + 512 * 256 + 12 * 512 * 256;
    k_prep_glu_all<<<(PREP_N + 255) / 256, 256>>>(Ws0, Ws1, Wu);
    k_prep_att_bn<<<(5 * 512 * 128 + 255) / 256, 256>>>(W_att, ft_g, ft_b, ft_m, ft_v,
                                                        att_g, att_b, att_m, att_v);
    k_init<<<(BATCH * FDIM) / 256, 256>>>(features, bn0_g, bn0_b, bn0_m, bn0_v);

    const dim3 gMma(4, BATCH / 64);

    auto ft_transformer = [&](int t, float* accOut) {
        const float* s0 = fts + (size_t)t * 4 * 512;
        const float* t0 = ftt + (size_t)t * 4 * 512;
        k_mma<<<gMma, 256, SMEM_TOTAL>>>(A, 512, 512, W0,
            s0, t0, nullptr, h0, nullptr);
        k_mma<<<gMma, 256, SMEM_TOTAL>>>(h0, 256, 256, W1,
            s0 + 512, t0 + 512, h0, h1, nullptr);
        k_mma<<<gMma, 256, SMEM_TOTAL>>>(h1, 256, 256,
            WU + (size_t)(t * 2 + 0) * 512 * 256,
            s0 + 1024, t0 + 1024, h1, h0, nullptr);
        k_mma<<<gMma, 256, SMEM_TOTAL>>>(h0, 256, 256,
            WU + (size_t)(t * 2 + 1) * 512 * 256,
            s0 + 1536, t0 + 1536, h0, h1, accOut);
    };

    ft_transformer(0, nullptr);

    for (int s = 0; s < STEPS; s++) {
        k_att<<<BATCH / 64, 512, ATT_SMEM>>>(h1 + 128, 256,
            WA + (size_t)s * 512 * 128,
            as + (size_t)s * 512, at + (size_t)s * 512,
            prior, masks + (size_t)s * BATCH * FDIM, A);
        ft_transformer(s + 1, acc);
    }

    k_fin<<<dim3(2, BATCH / 128), 256>>>(acc, Wf, bf, outF);
}

// round 14
// speedup vs baseline: 1.1413x; 1.1413x over previous
#include <cuda_runtime.h>
#include <cuda_fp16.h>
#include <math.h>
#include <stdint.h>

#define BATCH 32768
#define FDIM 512
#define HS 256
#define OUTD 128
#define STEPS 5
#define EPSBN 1e-5f

typedef __half fp16;

// ---------------- scratch (device globals; no allocation) ----------------
__device__ fp16  g_featsh[BATCH * FDIM];
__device__ fp16  g_A[BATCH * FDIM];
__device__ fp16  g_h0[BATCH * HS];
__device__ fp16  g_h1[BATCH * HS];
__device__ float g_z[BATCH * FDIM];
__device__ float g_prior[BATCH * FDIM];
__device__ float g_acc[BATCH * OUTD];

// prepped weights ([N,K] fp16; GLU ones N-permuted with 8-col a/b interleave)
__device__ fp16 g_W0[512 * 512];
__device__ fp16 g_W1[512 * 256];
__device__ fp16 g_WU[12 * 512 * 256];
__device__ fp16 g_WA[5 * 512 * 128];
__device__ float g_fts[6 * 4 * 512], g_ftt[6 * 4 * 512];
__device__ float g_as[5 * 512], g_at[5 * 512];

// ---------------- PTX helpers ----------------
__device__ __forceinline__ uint32_t smem_u32(const void* p) {
    uint32_t a;
    asm("{ .reg .u64 t; cvta.to.shared.u64 t, %1; cvt.u32.u64 %0, t; }" : "=r"(a) : "l"(p));
    return a;
}
__device__ __forceinline__ void cpa16(uint32_t s, const void* g) {
    asm volatile("cp.async.cg.shared.global [%0], [%1], 16;" :: "r"(s), "l"(g));
}
__device__ __forceinline__ void cpa_commit() {
    asm volatile("cp.async.commit_group;" ::: "memory");
}
template<int N>
__device__ __forceinline__ void cpa_wait() {
    asm volatile("cp.async.wait_group %0;" :: "n"(N) : "memory");
}
__device__ __forceinline__ void ldm4(uint32_t* v, uint32_t addr) {
    asm volatile("ldmatrix.sync.aligned.m8n8.x4.shared.b16 {%0,%1,%2,%3}, [%4];"
                 : "=r"(v[0]), "=r"(v[1]), "=r"(v[2]), "=r"(v[3]) : "r"(addr));
}
__device__ __forceinline__ void mma16(float* c, const uint32_t* a, uint32_t b0, uint32_t b1) {
    asm("mma.sync.aligned.m16n8k16.row.col.f32.f16.f16.f32 "
        "{%0,%1,%2,%3}, {%4,%5,%6,%7}, {%8,%9}, {%0,%1,%2,%3};"
        : "+f"(c[0]), "+f"(c[1]), "+f"(c[2]), "+f"(c[3])
        : "r"(a[0]), "r"(a[1]), "r"(a[2]), "r"(a[3]), "r"(b0), "r"(b1));
}

// ---------------- prep ----------------
__device__ __forceinline__ void prep_one(const float* W, int K, int idx, fp16* o)
{
    int n = idx / K, k = idx - n * K;
    int q = n >> 4, rr = n & 15, half = rr >> 3, jl = rr & 7;
    int col = (half ? 256 : 0) + q * 8 + jl;
    o[idx] = __float2half_rn(W[(size_t)k * 512 + col]);
}

__global__ void k_prep_glu_all(const float* __restrict__ Ws0,
                               const float* __restrict__ Ws1,
                               const float* __restrict__ Wu)
{
    int idx = blockIdx.x * 256 + threadIdx.x;
    const int N0 = 512 * 512;
    const int N1 = N0 + 512 * 256;
    const int N2 = N1 + 12 * 512 * 256;
    if (idx < N0) {
        prep_one(Ws0, 512, idx, g_W0);
    } else if (idx < N1) {
        prep_one(Ws1, 256, idx - N0, g_W1);
    } else if (idx < N2) {
        int r = idx - N1;
        int mi = r / (512 * 256);
        int li = r - mi * (512 * 256);
        prep_one(Wu + (size_t)mi * 256 * 512, 256, li, g_WU + (size_t)mi * 512 * 256);
    }
}

__global__ void k_prep_att_bn(const float* __restrict__ Wa,
                              const float* __restrict__ fg, const float* __restrict__ fb,
                              const float* __restrict__ fm, const float* __restrict__ fv,
                              const float* __restrict__ ag, const float* __restrict__ ab,
                              const float* __restrict__ am, const float* __restrict__ av)
{
    int idx = blockIdx.x * 256 + threadIdx.x;
    if (idx < 5 * 512 * 128) {
        int s = idx / (512 * 128);
        int r = idx - s * 512 * 128;
        int n = r >> 7, k = r & 127;
        g_WA[idx] = __float2half_rn(Wa[(size_t)s * 128 * 512 + (size_t)k * 512 + n]);
    }
    if (idx < 6 * 4 * 512) {
        float s = fg[idx] * rsqrtf(fv[idx] + EPSBN);
        g_fts[idx] = s;
        g_ftt[idx] = fb[idx] - fm[idx] * s;
    }
    if (idx < 5 * 512) {
        float s = ag[idx] * rsqrtf(av[idx] + EPSBN);
        g_as[idx] = s;
        g_at[idx] = ab[idx] - am[idx] * s;
    }
}

__global__ void k_init(const float* __restrict__ feat,
                       const float* __restrict__ g, const float* __restrict__ b,
                       const float* __restrict__ m, const float* __restrict__ v)
{
    int i = blockIdx.x * blockDim.x + threadIdx.x;
    if (i < BATCH * FDIM) {
        int c = i & (FDIM - 1);
        float f = g[c] * (feat[i] - m[c]) * rsqrtf(v[c] + EPSBN) + b[c];
        fp16 h = __float2half_rn(f);
        g_featsh[i] = h;
        g_A[i] = h;
        g_prior[i] = 1.0f;
        if (i < BATCH * OUTD) g_acc[i] = 0.0f;
    }
}

// ================= small-tile GEMM (R12 winner): MODE 0 GLU / MODE 1 att =====
// 256 threads, 3 CTAs/SM. BM=64, BN=128, BK=64. Warp grid 2(M)x4(N), tile 32x32.
#define STAGE_S 24576     // A 8K | B 16K
#define NSTAGE 3
#define PARAM_S (NSTAGE * STAGE_S)
#define SMEM_S  (PARAM_S + 1024)

template<int MODE>
__global__ __launch_bounds__(256, 3)
void k_mma_s(const fp16* __restrict__ A, int lda, int K,
             const fp16* __restrict__ B,
             const float* __restrict__ bs, const float* __restrict__ bt,
             const fp16* __restrict__ resh,
             fp16* __restrict__ outh,
             float* __restrict__ accp,
             const float* __restrict__ prior, float* __restrict__ zout)
{
    extern __shared__ __align__(128) char smem[];
    const int tid = threadIdx.x, wid = tid >> 5, lid = tid & 31;
    const int wm = wid >> 2, wn = wid & 3;
    const int g = blockIdx.x;
    const int row0 = blockIdx.y * 64;
    const uint32_t sb = smem_u32(smem);

    if (tid < 128) {
        float* sE = (float*)(smem + PARAM_S);
        float* tE = (float*)(smem + PARAM_S + 512);
        int col;
        if (MODE == 0) {
            int q2 = tid >> 4, rr = tid & 15, half = rr >> 3, jl = rr & 7;
            col = (half ? 256 : 0) + g * 64 + q2 * 8 + jl;
        } else {
            col = g * 128 + tid;
        }
        sE[tid] = bs[col];
        tE[tid] = bt[col];
    }

    float acc[8][4];
#pragma unroll
    for (int i = 0; i < 8; i++)
#pragma unroll
        for (int j = 0; j < 4; j++) acc[i][j] = 0.0f;

    const int nch = K >> 6;

    const char* gA[2];
    const char* gB[4];
    uint32_t soA[2], soB[4];
#pragma unroll
    for (int i = 0; i < 2; i++) {
        int idx = tid + i * 256;
        int r = idx >> 3, c = idx & 7;
        soA[i] = (uint32_t)(r * 128 + ((c ^ (r & 7)) << 4));
        gA[i] = (const char*)(A + (size_t)(row0 + r) * lda + c * 8);
    }
#pragma unroll
    for (int i = 0; i < 4; i++) {
        int idx = tid + i * 256;
        int r = idx >> 3, c = idx & 7;
        soB[i] = (uint32_t)(8192 + r * 128 + ((c ^ (r & 7)) << 4));
        gB[i] = (const char*)(B + (size_t)(g * 128 + r) * K + c * 8);
    }

    auto load_stage = [&](int ch) {
        const uint32_t st = sb + (ch % NSTAGE) * STAGE_S;
        const int kb = ch << 7;
#pragma unroll
        for (int i = 0; i < 2; i++) cpa16(st + soA[i], gA[i] + kb);
#pragma unroll
        for (int i = 0; i < 4; i++) cpa16(st + soB[i], gB[i] + kb);
    };

#pragma unroll
    for (int p = 0; p < 2; p++) {
        if (p < nch) load_stage(p);
        cpa_commit();
    }

    const int lr = lid & 15, lc = lid >> 4;
    uint32_t offA[2], offB2[2];
#pragma unroll
    for (int m = 0; m < 2; m++) {
        int r = wm * 32 + m * 16 + lr;
        offA[m] = (uint32_t)(r * 128 + ((lc ^ (r & 7)) << 4));
    }
#pragma unroll
    for (int q = 0; q < 2; q++) {
        int r = wn * 32 + q * 16 + lr;
        offB2[q] = (uint32_t)(8192 + r * 128 + ((lc ^ (r & 7)) << 4));
    }

    for (int ch = 0; ch < nch; ch++) {
        cpa_wait<1>();
        __syncthreads();
        if (ch + 2 < nch) load_stage(ch + 2);
        cpa_commit();

        const uint32_t st = sb + (ch % NSTAGE) * STAGE_S;
        uint32_t aH0 = st + offA[0], aH1 = st + offA[1];
        uint32_t aB0 = st + offB2[0], aB1 = st + offB2[1];

#pragma unroll
        for (int ks = 0; ks < 4; ks++) {
            uint32_t ah[2][4], bq[2][4];
            ldm4(ah[0], aH0); ldm4(ah[1], aH1);
            ldm4(bq[0], aB0); ldm4(bq[1], aB1);
#pragma unroll
            for (int m = 0; m < 2; m++) {
                mma16(acc[m * 4 + 0], ah[m], bq[0][0], bq[0][2]);
                mma16(acc[m * 4 + 1], ah[m], bq[0][1], bq[0][3]);
                mma16(acc[m * 4 + 2], ah[m], bq[1][0], bq[1][2]);
                mma16(acc[m * 4 + 3], ah[m], bq[1][1], bq[1][3]);
            }
            const uint32_t d = (ks & 1) ? 96u : 32u;
            aH0 ^= d; aH1 ^= d;
            aB0 ^= d; aB1 ^= d;
        }
    }

    const float* sE = (const float*)(smem + PARAM_S);
    const float* tE = (const float*)(smem + PARAM_S + 512);
    const int gid = lid >> 2, tp = lid & 3;

    if (MODE == 0) {
#pragma unroll
        for (int m = 0; m < 2; m++) {
#pragma unroll
            for (int t = 0; t < 2; t++) {
                const int ja = wn * 32 + t * 16 + tp * 2;
                const int jb = ja + 8;
                const int cn = g * 64 + (wn * 2 + t) * 8 + tp * 2;
                const float sa0 = sE[ja], sa1 = sE[ja + 1];
                const float ta0 = tE[ja], ta1 = tE[ja + 1];
                const float sb0 = sE[jb], sb1 = sE[jb + 1];
                const float tb0 = tE[jb], tb1 = tE[jb + 1];
                const float* ca = acc[m * 4 + 2 * t];
                const float* cb = acc[m * 4 + 2 * t + 1];
#pragma unroll
                for (int h = 0; h < 2; h++) {
                    const int row = row0 + wm * 32 + m * 16 + gid + h * 8;
                    float xa0 = ca[2 * h] * sa0 + ta0;
                    float xa1 = ca[2 * h + 1] * sa1 + ta1;
                    float xb0 = cb[2 * h] * sb0 + tb0;
                    float xb1 = cb[2 * h + 1] * sb1 + tb1;
                    float o0 = xa0 * (1.0f / (1.0f + __expf(-xb0)));
                    float o1 = xa1 * (1.0f / (1.0f + __expf(-xb1)));
                    const size_t ob = (size_t)row * HS + cn;
                    if (resh) {
                        __half2 rh = *(const __half2*)(resh + ob);
                        o0 = fmaf(__half2float(rh.x), 0.70710678118654752f, o0);
                        o1 = fmaf(__half2float(rh.y), 0.70710678118654752f, o1);
                    }
                    __half2 hh;
                    hh.x = __float2half_rn(o0);
                    hh.y = __float2half_rn(o1);
                    *(__half2*)(outh + ob) = hh;
                    if (accp && g < 2) {
                        float2* ap = (float2*)(accp + (size_t)row * OUTD + cn);
                        float2 av = *ap;
                        av.x += fmaxf(o0, 0.0f);
                        av.y += fmaxf(o1, 0.0f);
                        *ap = av;
                    }
                }
            }
        }
    } else {
#pragma unroll
        for (int m = 0; m < 2; m++) {
#pragma unroll
            for (int nb = 0; nb < 4; nb++) {
                const int cn = wn * 32 + nb * 8 + tp * 2;
                const float s0 = sE[cn], s1 = sE[cn + 1];
                const float t0 = tE[cn], t1 = tE[cn + 1];
                const float* ca = acc[m * 4 + nb];
#pragma unroll
                for (int h = 0; h < 2; h++) {
                    const int row = row0 + wm * 32 + m * 16 + gid + h * 8;
                    const size_t idx = (size_t)row * FDIM + g * 128 + cn;
                    float2 pr = *(const float2*)(prior + idx);
                    float2 zz;
                    zz.x = (ca[2 * h] * s0 + t0) * pr.x;
                    zz.y = (ca[2 * h + 1] * s1 + t1) * pr.y;
                    *(float2*)(zout + idx) = zz;
                }
            }
        }
    }
}

// ================= big-tile GEMM (R11 winner) for K=512 block-0 ==============
// 256 threads, 2 CTAs/SM. BM=128, BN=128, BK=64. Warp grid 4(M)x2(N), tile 32x64.
#define STAGE_B 32768     // A 16K | B 16K
#define PARAM_B (NSTAGE * STAGE_B)
#define SMEM_B  (PARAM_B + 1024)

__global__ __launch_bounds__(256, 2)
void k_mma_b(const fp16* __restrict__ A, int lda, int K,
             const fp16* __restrict__ B,
             const float* __restrict__ bs, const float* __restrict__ bt,
             fp16* __restrict__ outh)
{
    extern __shared__ __align__(128) char smem[];
    const int tid = threadIdx.x, wid = tid >> 5, lid = tid & 31;
    const int wm = wid >> 1, wn = wid & 1;
    const int g = blockIdx.x;
    const int row0 = blockIdx.y * 128;
    const uint32_t sb = smem_u32(smem);

    if (tid < 128) {
        float* sE = (float*)(smem + PARAM_B);
        float* tE = (float*)(smem + PARAM_B + 512);
        int q2 = tid >> 4, rr = tid & 15, half = rr >> 3, jl = rr & 7;
        int col = (half ? 256 : 0) + g * 64 + q2 * 8 + jl;
        sE[tid] = bs[col];
        tE[tid] = bt[col];
    }

    float acc[16][4];
#pragma unroll
    for (int i = 0; i < 16; i++)
#pragma unroll
        for (int j = 0; j < 4; j++) acc[i][j] = 0.0f;

    const int nch = K >> 6;

    const char* gA[4];
    const char* gB[4];
    uint32_t soA[4], soB[4];
#pragma unroll
    for (int i = 0; i < 4; i++) {
        int idx = tid + i * 256;
        int r = idx >> 3, c = idx & 7;
        uint32_t so = (uint32_t)(r * 128 + ((c ^ (r & 7)) << 4));
        soA[i] = so;
        soB[i] = 16384u + so;
        gA[i] = (const char*)(A + (size_t)(row0 + r) * lda + c * 8);
        gB[i] = (const char*)(B + (size_t)(g * 128 + r) * K + c * 8);
    }

    auto load_stage = [&](int ch) {
        const uint32_t st = sb + (ch % NSTAGE) * STAGE_B;
        const int kb = ch << 7;
#pragma unroll
        for (int i = 0; i < 4; i++) {
            cpa16(st + soA[i], gA[i] + kb);
            cpa16(st + soB[i], gB[i] + kb);
        }
    };

#pragma unroll
    for (int p = 0; p < 2; p++) {
        if (p < nch) load_stage(p);
        cpa_commit();
    }

    const int lr = lid & 15, lc = lid >> 4;
    uint32_t offA[2], offB4[4];
#pragma unroll
    for (int m = 0; m < 2; m++) {
        int r = wm * 32 + m * 16 + lr;
        offA[m] = (uint32_t)(r * 128 + ((lc ^ (r & 7)) << 4));
    }
#pragma unroll
    for (int nb = 0; nb < 4; nb++) {
        int r = wn * 64 + nb * 16 + lr;
        offB4[nb] = (uint32_t)(16384 + r * 128 + ((lc ^ (r & 7)) << 4));
    }

    for (int ch = 0; ch < nch; ch++) {
        cpa_wait<1>();
        __syncthreads();
        if (ch + 2 < nch) load_stage(ch + 2);
        cpa_commit();

        const uint32_t st = sb + (ch % NSTAGE) * STAGE_B;
        uint32_t aH0 = st + offA[0], aH1 = st + offA[1];
        uint32_t aB0 = st + offB4[0], aB1 = st + offB4[1];
        uint32_t aB2 = st + offB4[2], aB3 = st + offB4[3];

#pragma unroll
        for (int ks = 0; ks < 4; ks++) {
            uint32_t ah[2][4], bq[4][4];
            ldm4(ah[0], aH0); ldm4(ah[1], aH1);
            ldm4(bq[0], aB0); ldm4(bq[1], aB1);
            ldm4(bq[2], aB2); ldm4(bq[3], aB3);
#pragma unroll
            for (int nb = 0; nb < 4; nb++)
#pragma unroll
                for (int m = 0; m < 2; m++) {
                    mma16(acc[m * 8 + 2 * nb],     ah[m], bq[nb][0], bq[nb][2]);
                    mma16(acc[m * 8 + 2 * nb + 1], ah[m], bq[nb][1], bq[nb][3]);
                }
            const uint32_t d = (ks & 1) ? 96u : 32u;
            aH0 ^= d; aH1 ^= d;
            aB0 ^= d; aB1 ^= d; aB2 ^= d; aB3 ^= d;
        }
    }

    const float* sE = (const float*)(smem + PARAM_B);
    const float* tE = (const float*)(smem + PARAM_B + 512);
    const int gid = lid >> 2, tp = lid & 3;

#pragma unroll
    for (int m = 0; m < 2; m++) {
#pragma unroll
        for (int t = 0; t < 4; t++) {
            const int ja = wn * 64 + t * 16 + tp * 2;
            const int jb = ja + 8;
            const int cn = g * 64 + (wn * 4 + t) * 8 + tp * 2;
            const float sa0 = sE[ja], sa1 = sE[ja + 1];
            const float ta0 = tE[ja], ta1 = tE[ja + 1];
            const float sb0 = sE[jb], sb1 = sE[jb + 1];
            const float tb0 = tE[jb], tb1 = tE[jb + 1];
            const float* ca = acc[m * 8 + 2 * t];
            const float* cb = acc[m * 8 + 2 * t + 1];
#pragma unroll
            for (int h = 0; h < 2; h++) {
                const int row = row0 + wm * 32 + m * 16 + gid + h * 8;
                float xa0 = ca[2 * h] * sa0 + ta0;
                float xa1 = ca[2 * h + 1] * sa1 + ta1;
                float xb0 = cb[2 * h] * sb0 + tb0;
                float xb1 = cb[2 * h + 1] * sb1 + tb1;
                float o0 = xa0 * (1.0f / (1.0f + __expf(-xb0)));
                float o1 = xa1 * (1.0f / (1.0f + __expf(-xb1)));
                const size_t ob = (size_t)row * HS + cn;
                __half2 hh;
                hh.x = __float2half_rn(o0);
                hh.y = __float2half_rn(o1);
                *(__half2*)(outh + ob) = hh;
            }
        }
    }
}

// ---------------- sparsemax: one warp per row ----------------
__global__ __launch_bounds__(256)
void k_sparsemax(const float* __restrict__ z, float* __restrict__ prior,
                 float* __restrict__ maskOut, fp16* __restrict__ mf)
{
    const int row = blockIdx.x * 8 + (threadIdx.x >> 5);
    const int lid = threadIdx.x & 31;
    const size_t base = (size_t)row * 512;
    float v[16];
#pragma unroll
    for (int q = 0; q < 4; q++) {
        float4 t = *(const float4*)(z + base + q * 128 + lid * 4);
        v[q * 4 + 0] = t.x; v[q * 4 + 1] = t.y; v[q * 4 + 2] = t.z; v[q * 4 + 3] = t.w;
    }
    float zmax = v[0];
#pragma unroll
    for (int i = 1; i < 16; i++) zmax = fmaxf(zmax, v[i]);
#pragma unroll
    for (int o = 16; o; o >>= 1) zmax = fmaxf(zmax, __shfl_xor_sync(0xffffffffu, zmax, o));

    float lo = zmax - 1.0f, hi = zmax;
    for (int it = 0; it < 20; it++) {
        float mid = 0.5f * (lo + hi);
        float s = 0.0f;
#pragma unroll
        for (int i = 0; i < 16; i++) s += fmaxf(v[i] - mid, 0.0f);
#pragma unroll
        for (int o = 16; o; o >>= 1) s += __shfl_xor_sync(0xffffffffu, s, o);
        if (s >= 1.0f) lo = mid; else hi = mid;
    }
    float sum = 0.0f, cnt = 0.0f;
#pragma unroll
    for (int i = 0; i < 16; i++) {
        if (v[i] > lo) { sum += v[i]; cnt += 1.0f; }
    }
#pragma unroll
    for (int o = 16; o; o >>= 1) {
        sum += __shfl_xor_sync(0xffffffffu, sum, o);
        cnt += __shfl_xor_sync(0xffffffffu, cnt, o);
    }
    const float tau = (sum - 1.0f) / cnt;

#pragma unroll
    for (int q = 0; q < 4; q++) {
        const size_t off = base + q * 128 + lid * 4;
        float4 mk;
        mk.x = fmaxf(v[q * 4 + 0] - tau, 0.0f);
        mk.y = fmaxf(v[q * 4 + 1] - tau, 0.0f);
        mk.z = fmaxf(v[q * 4 + 2] - tau, 0.0f);
        mk.w = fmaxf(v[q * 4 + 3] - tau, 0.0f);
        *(float4*)(maskOut + off) = mk;
        float4 pr = *(const float4*)(prior + off);
        pr.x *= (1.5f - mk.x); pr.y *= (1.5f - mk.y);
        pr.z *= (1.5f - mk.z); pr.w *= (1.5f - mk.w);
        *(float4*)(prior + off) = pr;
        __half2 f01 = *(const __half2*)(g_featsh + off);
        __half2 f23 = *(const __half2*)(g_featsh + off + 2);
        __half2 p0, p1;
        p0.x = __float2half_rn(mk.x * __half2float(f01.x));
        p0.y = __float2half_rn(mk.y * __half2float(f01.y));
        p1.x = __float2half_rn(mk.z * __half2float(f23.x));
        p1.y = __float2half_rn(mk.w * __half2float(f23.y));
        *(__half2*)(mf + off) = p0;
        *(__half2*)(mf + off + 2) = p1;
    }
}

// ---------------- final projection ----------------
__global__ __launch_bounds__(256)
void k_fin(const float* __restrict__ A, const float* __restrict__ W,
           const float* __restrict__ bias, float* __restrict__ C)
{
    __shared__ float As[16][128];
    __shared__ float Ws[16][64];
    const int tid = threadIdx.x;
    const int ty = tid >> 4, tx = tid & 15;
    const int row0 = blockIdx.y * 128;
    const int col0 = blockIdx.x * 64;

    float acc[8][4];
#pragma unroll
    for (int r = 0; r < 8; r++)
#pragma unroll
        for (int c = 0; c < 4; c++) acc[r][c] = 0.f;

    for (int kt = 0; kt < 128; kt += 16) {
#pragma unroll
        for (int l = 0; l < 2; l++) {
            int li = tid * 2 + l;
            int r = li >> 2, kq = (li & 3) * 4;
            float4 av = *(const float4*)(A + (size_t)(row0 + r) * 128 + kt + kq);
            As[kq + 0][r] = av.x; As[kq + 1][r] = av.y;
            As[kq + 2][r] = av.z; As[kq + 3][r] = av.w;
        }
        *(float4*)&Ws[tid >> 4][(tid & 15) * 4] =
            *(const float4*)(W + (size_t)(kt + (tid >> 4)) * 128 + col0 + (tid & 15) * 4);
        __syncthreads();
#pragma unroll
        for (int kk = 0; kk < 16; kk++) {
            float a[8];
            float4 a0 = *(float4*)&As[kk][ty * 8];
            float4 a1 = *(float4*)&As[kk][ty * 8 + 4];
            a[0] = a0.x; a[1] = a0.y; a[2] = a0.z; a[3] = a0.w;
            a[4] = a1.x; a[5] = a1.y; a[6] = a1.z; a[7] = a1.w;
            float4 w0 = *(float4*)&Ws[kk][tx * 4];
            float wv[4] = {w0.x, w0.y, w0.z, w0.w};
#pragma unroll
            for (int r = 0; r < 8; r++)
#pragma unroll
                for (int c = 0; c < 4; c++) acc[r][c] += a[r] * wv[c];
        }
        __syncthreads();
    }
#pragma unroll
    for (int r = 0; r < 8; r++) {
        int gr = row0 + ty * 8 + r;
#pragma unroll
        for (int c = 0; c < 4; c++) {
            int gc = col0 + tx * 4 + c;
            C[(size_t)gr * 128 + gc] = acc[r][c] + bias[gc];
        }
    }
}

// ---------------- launch ----------------
extern "C" void kernel_launch(void* const* d_in, const int* in_sizes, int n_in,
                              void* d_out, int out_size)
{
    const float* features = (const float*)d_in[0];
    const float* bn0_g = (const float*)d_in[1];
    const float* bn0_b = (const float*)d_in[2];
    const float* bn0_m = (const float*)d_in[3];
    const float* bn0_v = (const float*)d_in[4];
    const float* Ws0   = (const float*)d_in[5];
    const float* Ws1   = (const float*)d_in[6];
    const float* Wu    = (const float*)d_in[7];
    const float* ft_g  = (const float*)d_in[8];
    const float* ft_b  = (const float*)d_in[9];
    const float* ft_m  = (const float*)d_in[10];
    const float* ft_v  = (const float*)d_in[11];
    const float* W_att = (const float*)d_in[12];
    const float* att_g = (const float*)d_in[13];
    const float* att_b = (const float*)d_in[14];
    const float* att_m = (const float*)d_in[15];
    const float* att_v = (const float*)d_in[16];
    const float* Wf    = (const float*)d_in[17];
    const float* bf    = (const float*)d_in[18];

    float *zp, *prior, *acc;
    fp16 *A, *h0, *h1;
    fp16 *W0, *W1, *WU, *WA;
    float *fts, *ftt, *as, *at;
    cudaGetSymbolAddress((void**)&A, g_A);
    cudaGetSymbolAddress((void**)&h0, g_h0);
    cudaGetSymbolAddress((void**)&h1, g_h1);
    cudaGetSymbolAddress((void**)&zp, g_z);
    cudaGetSymbolAddress((void**)&prior, g_prior);
    cudaGetSymbolAddress((void**)&acc, g_acc);
    cudaGetSymbolAddress((void**)&W0, g_W0);
    cudaGetSymbolAddress((void**)&W1, g_W1);
    cudaGetSymbolAddress((void**)&WU, g_WU);
    cudaGetSymbolAddress((void**)&WA, g_WA);
    cudaGetSymbolAddress((void**)&fts, g_fts);
    cudaGetSymbolAddress((void**)&ftt, g_ftt);
    cudaGetSymbolAddress((void**)&as, g_as);
    cudaGetSymbolAddress((void**)&at, g_at);

    float* outF  = (float*)d_out;
    float* masks = outF + (size_t)BATCH * OUTD;

    static bool attr_set = false;
    if (!attr_set) {
        cudaFuncSetAttribute(k_mma_s<0>, cudaFuncAttributeMaxDynamicSharedMemorySize, SMEM_S);
        cudaFuncSetAttribute(k_mma_s<1>, cudaFuncAttributeMaxDynamicSharedMemorySize, SMEM_S);
        cudaFuncSetAttribute(k_mma_b, cudaFuncAttributeMaxDynamicSharedMemorySize, SMEM_B);
        attr_set = true;
    }

    const int PREP_N = 512 * 512 + 512 * 256 + 12 * 512 * 256;
    k_prep_glu_all<<<(PREP_N + 255) / 256, 256>>>(Ws0, Ws1, Wu);
    k_prep_att_bn<<<(5 * 512 * 128 + 255) / 256, 256>>>(W_att, ft_g, ft_b, ft_m, ft_v,
                                                        att_g, att_b, att_m, att_v);
    k_init<<<(BATCH * FDIM) / 256, 256>>>(features, bn0_g, bn0_b, bn0_m, bn0_v);

    const dim3 gS(4, BATCH / 64);
    const dim3 gB(4, BATCH / 128);

    auto ft_transformer = [&](int t, float* accOut) {
        const float* s0 = fts + (size_t)t * 4 * 512;
        const float* t0 = ftt + (size_t)t * 4 * 512;
        // block 0 (K=512): big-tile kernel
        k_mma_b<<<gB, 256, SMEM_B>>>(A, 512, 512, W0, s0, t0, h0);
        // blocks 1-3 (K=256): small-tile kernel
        k_mma_s<0><<<gS, 256, SMEM_S>>>(h0, 256, 256, W1,
            s0 + 512, t0 + 512, h0, h1, nullptr, nullptr, nullptr);
        k_mma_s<0><<<gS, 256, SMEM_S>>>(h1, 256, 256,
            WU + (size_t)(t * 2 + 0) * 512 * 256,
            s0 + 1024, t0 + 1024, h1, h0, nullptr, nullptr, nullptr);
        k_mma_s<0><<<gS, 256, SMEM_S>>>(h0, 256, 256,
            WU + (size_t)(t * 2 + 1) * 512 * 256,
            s0 + 1536, t0 + 1536, h0, h1, accOut, nullptr, nullptr);
    };

    ft_transformer(0, nullptr);

    for (int s = 0; s < STEPS; s++) {
        k_mma_s<1><<<gS, 256, SMEM_S>>>(h1 + 128, 256, 128,
            WA + (size_t)s * 512 * 128,
            as + (size_t)s * 512, at + (size_t)s * 512,
            nullptr, nullptr, nullptr,
            prior, zp);
        k_sparsemax<<<BATCH / 8, 256>>>(zp, prior, masks + (size_t)s * BATCH * FDIM, A);
        ft_transformer(s + 1, acc);
    }

    k_fin<<<dim3(2, BATCH / 128), 256>>>(acc, Wf, bf, outF);
}

// round 15
// speedup vs baseline: 1.1692x; 1.0245x over previous
#include <cuda_runtime.h>
#include <cuda_fp16.h>
#include <math.h>
#include <stdint.h>

#define BATCH 32768
#define FDIM 512
#define HS 256
#define OUTD 128
#define STEPS 5
#define EPSBN 1e-5f

typedef __half fp16;

// ---------------- scratch (device globals; no allocation) ----------------
__device__ fp16  g_featsh[BATCH * FDIM];
__device__ fp16  g_A[BATCH * FDIM];
__device__ fp16  g_h0[BATCH * HS];
__device__ fp16  g_h1[BATCH * HS];
__device__ float g_z[BATCH * FDIM];
__device__ float g_prior[BATCH * FDIM];
__device__ float g_acc[BATCH * OUTD];

// prepped weights ([N,K] fp16; GLU ones N-permuted with 8-col a/b interleave)
__device__ fp16 g_W0[512 * 512];
__device__ fp16 g_W1[512 * 256];
__device__ fp16 g_WU[12 * 512 * 256];
__device__ fp16 g_WA[5 * 512 * 128];
__device__ float g_fts[6 * 4 * 512], g_ftt[6 * 4 * 512];
__device__ float g_as[5 * 512], g_at[5 * 512];

// ---------------- PTX helpers ----------------
__device__ __forceinline__ uint32_t smem_u32(const void* p) {
    uint32_t a;
    asm("{ .reg .u64 t; cvta.to.shared.u64 t, %1; cvt.u32.u64 %0, t; }" : "=r"(a) : "l"(p));
    return a;
}
__device__ __forceinline__ void cpa16(uint32_t s, const void* g) {
    asm volatile("cp.async.cg.shared.global [%0], [%1], 16;" :: "r"(s), "l"(g));
}
__device__ __forceinline__ void cpa_commit() {
    asm volatile("cp.async.commit_group;" ::: "memory");
}
template<int N>
__device__ __forceinline__ void cpa_wait() {
    asm volatile("cp.async.wait_group %0;" :: "n"(N) : "memory");
}
__device__ __forceinline__ void ldm4(uint32_t* v, uint32_t addr) {
    asm volatile("ldmatrix.sync.aligned.m8n8.x4.shared.b16 {%0,%1,%2,%3}, [%4];"
                 : "=r"(v[0]), "=r"(v[1]), "=r"(v[2]), "=r"(v[3]) : "r"(addr));
}
__device__ __forceinline__ void mma16(float* c, const uint32_t* a, uint32_t b0, uint32_t b1) {
    asm("mma.sync.aligned.m16n8k16.row.col.f32.f16.f16.f32 "
        "{%0,%1,%2,%3}, {%4,%5,%6,%7}, {%8,%9}, {%0,%1,%2,%3};"
        : "+f"(c[0]), "+f"(c[1]), "+f"(c[2]), "+f"(c[3])
        : "r"(a[0]), "r"(a[1]), "r"(a[2]), "r"(a[3]), "r"(b0), "r"(b1));
}

// ---------------- fused setup: weight prep + bn prep + init (1 launch) -------
__device__ __forceinline__ void prep_one(const float* W, int K, int idx, fp16* o)
{
    int n = idx / K, k = idx - n * K;
    int q = n >> 4, rr = n & 15, half = rr >> 3, jl = rr & 7;
    int col = (half ? 256 : 0) + q * 8 + jl;
    o[idx] = __float2half_rn(W[(size_t)k * 512 + col]);
}

#define INIT_BLK  (BATCH * FDIM / 256)                       // 65536
#define PREPG_N   (512 * 512 + 512 * 256 + 12 * 512 * 256)   // 4325376
#define PREPG_BLK ((PREPG_N + 255) / 256)                    // 16896
#define PREPA_N   (5 * 512 * 128)                            // 327680
#define PREPA_BLK ((PREPA_N + 255) / 256)                    // 1280
#define SETUP_BLK (INIT_BLK + PREPG_BLK + PREPA_BLK)

__global__ void k_setup(const float* __restrict__ feat,
                        const float* __restrict__ g0, const float* __restrict__ b0,
                        const float* __restrict__ m0, const float* __restrict__ v0,
                        const float* __restrict__ Ws0,
                        const float* __restrict__ Ws1,
                        const float* __restrict__ Wu,
                        const float* __restrict__ Wa,
                        const float* __restrict__ fg, const float* __restrict__ fb,
                        const float* __restrict__ fm, const float* __restrict__ fv,
                        const float* __restrict__ ag, const float* __restrict__ ab,
                        const float* __restrict__ am, const float* __restrict__ av)
{
    const int b = blockIdx.x;
    if (b < INIT_BLK) {
        int i = b * 256 + threadIdx.x;
        int c = i & (FDIM - 1);
        float f = g0[c] * (feat[i] - m0[c]) * rsqrtf(v0[c] + EPSBN) + b0[c];
        fp16 h = __float2half_rn(f);
        g_featsh[i] = h;
        g_A[i] = h;
        if (i < BATCH * OUTD) g_acc[i] = 0.0f;
        return;
    }
    if (b < INIT_BLK + PREPG_BLK) {
        int idx = (b - INIT_BLK) * 256 + threadIdx.x;
        const int N0 = 512 * 512;
        const int N1 = N0 + 512 * 256;
        if (idx < N0) {
            prep_one(Ws0, 512, idx, g_W0);
        } else if (idx < N1) {
            prep_one(Ws1, 256, idx - N0, g_W1);
        } else if (idx < PREPG_N) {
            int r = idx - N1;
            int mi = r / (512 * 256);
            int li = r - mi * (512 * 256);
            prep_one(Wu + (size_t)mi * 256 * 512, 256, li, g_WU + (size_t)mi * 512 * 256);
        }
        return;
    }
    {
        int idx = (b - INIT_BLK - PREPG_BLK) * 256 + threadIdx.x;
        if (idx < PREPA_N) {
            int s = idx / (512 * 128);
            int r = idx - s * 512 * 128;
            int n = r >> 7, k = r & 127;
            g_WA[idx] = __float2half_rn(Wa[(size_t)s * 128 * 512 + (size_t)k * 512 + n]);
        }
        if (idx < 6 * 4 * 512) {
            float s = fg[idx] * rsqrtf(fv[idx] + EPSBN);
            g_fts[idx] = s;
            g_ftt[idx] = fb[idx] - fm[idx] * s;
        }
        if (idx < 5 * 512) {
            float s = ag[idx] * rsqrtf(av[idx] + EPSBN);
            g_as[idx] = s;
            g_at[idx] = ab[idx] - am[idx] * s;
        }
    }
}

// ================= small-tile GEMM: MODE 0 GLU / MODE 1 att (PR: use prior) ==
// 256 threads, 3 CTAs/SM. BM=64, BN=128, BK=64. Warp grid 2(M)x4(N), tile 32x32.
#define STAGE_S 24576     // A 8K | B 16K
#define NSTAGE 3
#define PARAM_S (NSTAGE * STAGE_S)
#define SMEM_S  (PARAM_S + 1024)

template<int MODE, int PR>
__global__ __launch_bounds__(256, 3)
void k_mma_s(const fp16* __restrict__ A, int lda, int K,
             const fp16* __restrict__ B,
             const float* __restrict__ bs, const float* __restrict__ bt,
             const fp16* __restrict__ resh,
             fp16* __restrict__ outh,
             float* __restrict__ accp,
             const float* __restrict__ prior, float* __restrict__ zout)
{
    extern __shared__ __align__(128) char smem[];
    const int tid = threadIdx.x, wid = tid >> 5, lid = tid & 31;
    const int wm = wid >> 2, wn = wid & 3;
    const int g = blockIdx.x;
    const int row0 = blockIdx.y * 64;
    const uint32_t sb = smem_u32(smem);

    if (tid < 128) {
        float* sE = (float*)(smem + PARAM_S);
        float* tE = (float*)(smem + PARAM_S + 512);
        int col;
        if (MODE == 0) {
            int q2 = tid >> 4, rr = tid & 15, half = rr >> 3, jl = rr & 7;
            col = (half ? 256 : 0) + g * 64 + q2 * 8 + jl;
        } else {
            col = g * 128 + tid;
        }
        sE[tid] = bs[col];
        tE[tid] = bt[col];
    }

    float acc[8][4];
#pragma unroll
    for (int i = 0; i < 8; i++)
#pragma unroll
        for (int j = 0; j < 4; j++) acc[i][j] = 0.0f;

    const int nch = K >> 6;

    const char* gA[2];
    const char* gB[4];
    uint32_t soA[2], soB[4];
#pragma unroll
    for (int i = 0; i < 2; i++) {
        int idx = tid + i * 256;
        int r = idx >> 3, c = idx & 7;
        soA[i] = (uint32_t)(r * 128 + ((c ^ (r & 7)) << 4));
        gA[i] = (const char*)(A + (size_t)(row0 + r) * lda + c * 8);
    }
#pragma unroll
    for (int i = 0; i < 4; i++) {
        int idx = tid + i * 256;
        int r = idx >> 3, c = idx & 7;
        soB[i] = (uint32_t)(8192 + r * 128 + ((c ^ (r & 7)) << 4));
        gB[i] = (const char*)(B + (size_t)(g * 128 + r) * K + c * 8);
    }

    auto load_stage = [&](int ch) {
        const uint32_t st = sb + (ch % NSTAGE) * STAGE_S;
        const int kb = ch << 7;
#pragma unroll
        for (int i = 0; i < 2; i++) cpa16(st + soA[i], gA[i] + kb);
#pragma unroll
        for (int i = 0; i < 4; i++) cpa16(st + soB[i], gB[i] + kb);
    };

#pragma unroll
    for (int p = 0; p < 2; p++) {
        if (p < nch) load_stage(p);
        cpa_commit();
    }

    const int lr = lid & 15, lc = lid >> 4;
    uint32_t offA[2], offB2[2];
#pragma unroll
    for (int m = 0; m < 2; m++) {
        int r = wm * 32 + m * 16 + lr;
        offA[m] = (uint32_t)(r * 128 + ((lc ^ (r & 7)) << 4));
    }
#pragma unroll
    for (int q = 0; q < 2; q++) {
        int r = wn * 32 + q * 16 + lr;
        offB2[q] = (uint32_t)(8192 + r * 128 + ((lc ^ (r & 7)) << 4));
    }

    for (int ch = 0; ch < nch; ch++) {
        cpa_wait<1>();
        __syncthreads();
        if (ch + 2 < nch) load_stage(ch + 2);
        cpa_commit();

        const uint32_t st = sb + (ch % NSTAGE) * STAGE_S;
        uint32_t aH0 = st + offA[0], aH1 = st + offA[1];
        uint32_t aB0 = st + offB2[0], aB1 = st + offB2[1];

#pragma unroll
        for (int ks = 0; ks < 4; ks++) {
            uint32_t ah[2][4], bq[2][4];
            ldm4(ah[0], aH0); ldm4(ah[1], aH1);
            ldm4(bq[0], aB0); ldm4(bq[1], aB1);
#pragma unroll
            for (int m = 0; m < 2; m++) {
                mma16(acc[m * 4 + 0], ah[m], bq[0][0], bq[0][2]);
                mma16(acc[m * 4 + 1], ah[m], bq[0][1], bq[0][3]);
                mma16(acc[m * 4 + 2], ah[m], bq[1][0], bq[1][2]);
                mma16(acc[m * 4 + 3], ah[m], bq[1][1], bq[1][3]);
            }
            const uint32_t d = (ks & 1) ? 96u : 32u;
            aH0 ^= d; aH1 ^= d;
            aB0 ^= d; aB1 ^= d;
        }
    }

    const float* sE = (const float*)(smem + PARAM_S);
    const float* tE = (const float*)(smem + PARAM_S + 512);
    const int gid = lid >> 2, tp = lid & 3;

    if (MODE == 0) {
#pragma unroll
        for (int m = 0; m < 2; m++) {
#pragma unroll
            for (int t = 0; t < 2; t++) {
                const int ja = wn * 32 + t * 16 + tp * 2;
                const int jb = ja + 8;
                const int cn = g * 64 + (wn * 2 + t) * 8 + tp * 2;
                const float sa0 = sE[ja], sa1 = sE[ja + 1];
                const float ta0 = tE[ja], ta1 = tE[ja + 1];
                const float sb0 = sE[jb], sb1 = sE[jb + 1];
                const float tb0 = tE[jb], tb1 = tE[jb + 1];
                const float* ca = acc[m * 4 + 2 * t];
                const float* cb = acc[m * 4 + 2 * t + 1];
#pragma unroll
                for (int h = 0; h < 2; h++) {
                    const int row = row0 + wm * 32 + m * 16 + gid + h * 8;
                    float xa0 = ca[2 * h] * sa0 + ta0;
                    float xa1 = ca[2 * h + 1] * sa1 + ta1;
                    float xb0 = cb[2 * h] * sb0 + tb0;
                    float xb1 = cb[2 * h + 1] * sb1 + tb1;
                    float o0 = xa0 * (1.0f / (1.0f + __expf(-xb0)));
                    float o1 = xa1 * (1.0f / (1.0f + __expf(-xb1)));
                    const size_t ob = (size_t)row * HS + cn;
                    if (resh) {
                        __half2 rh = *(const __half2*)(resh + ob);
                        o0 = fmaf(__half2float(rh.x), 0.70710678118654752f, o0);
                        o1 = fmaf(__half2float(rh.y), 0.70710678118654752f, o1);
                    }
                    __half2 hh;
                    hh.x = __float2half_rn(o0);
                    hh.y = __float2half_rn(o1);
                    *(__half2*)(outh + ob) = hh;
                    if (accp && g < 2) {
                        float2* ap = (float2*)(accp + (size_t)row * OUTD + cn);
                        float2 av = *ap;
                        av.x += fmaxf(o0, 0.0f);
                        av.y += fmaxf(o1, 0.0f);
                        *ap = av;
                    }
                }
            }
        }
    } else {
#pragma unroll
        for (int m = 0; m < 2; m++) {
#pragma unroll
            for (int nb = 0; nb < 4; nb++) {
                const int cn = wn * 32 + nb * 8 + tp * 2;
                const float s0 = sE[cn], s1 = sE[cn + 1];
                const float t0 = tE[cn], t1 = tE[cn + 1];
                const float* ca = acc[m * 4 + nb];
#pragma unroll
                for (int h = 0; h < 2; h++) {
                    const int row = row0 + wm * 32 + m * 16 + gid + h * 8;
                    const size_t idx = (size_t)row * FDIM + g * 128 + cn;
                    float2 zz;
                    zz.x = ca[2 * h] * s0 + t0;
                    zz.y = ca[2 * h + 1] * s1 + t1;
                    if (PR) {
                        float2 pr = *(const float2*)(prior + idx);
                        zz.x *= pr.x;
                        zz.y *= pr.y;
                    }
                    *(float2*)(zout + idx) = zz;
                }
            }
        }
    }
}

// ================= big-tile GEMM for K=512 block-0 ==========================
// 256 threads, 2 CTAs/SM. BM=128, BN=128, BK=64. Warp grid 4(M)x2(N), tile 32x64.
#define STAGE_B 32768     // A 16K | B 16K
#define PARAM_B (NSTAGE * STAGE_B)
#define SMEM_B  (PARAM_B + 1024)

__global__ __launch_bounds__(256, 2)
void k_mma_b(const fp16* __restrict__ A, int lda, int K,
             const fp16* __restrict__ B,
             const float* __restrict__ bs, const float* __restrict__ bt,
             fp16* __restrict__ outh)
{
    extern __shared__ __align__(128) char smem[];
    const int tid = threadIdx.x, wid = tid >> 5, lid = tid & 31;
    const int wm = wid >> 1, wn = wid & 1;
    const int g = blockIdx.x;
    const int row0 = blockIdx.y * 128;
    const uint32_t sb = smem_u32(smem);

    if (tid < 128) {
        float* sE = (float*)(smem + PARAM_B);
        float* tE = (float*)(smem + PARAM_B + 512);
        int q2 = tid >> 4, rr = tid & 15, half = rr >> 3, jl = rr & 7;
        int col = (half ? 256 : 0) + g * 64 + q2 * 8 + jl;
        sE[tid] = bs[col];
        tE[tid] = bt[col];
    }

    float acc[16][4];
#pragma unroll
    for (int i = 0; i < 16; i++)
#pragma unroll
        for (int j = 0; j < 4; j++) acc[i][j] = 0.0f;

    const int nch = K >> 6;

    const char* gA[4];
    const char* gB[4];
    uint32_t soA[4], soB[4];
#pragma unroll
    for (int i = 0; i < 4; i++) {
        int idx = tid + i * 256;
        int r = idx >> 3, c = idx & 7;
        uint32_t so = (uint32_t)(r * 128 + ((c ^ (r & 7)) << 4));
        soA[i] = so;
        soB[i] = 16384u + so;
        gA[i] = (const char*)(A + (size_t)(row0 + r) * lda + c * 8);
        gB[i] = (const char*)(B + (size_t)(g * 128 + r) * K + c * 8);
    }

    auto load_stage = [&](int ch) {
        const uint32_t st = sb + (ch % NSTAGE) * STAGE_B;
        const int kb = ch << 7;
#pragma unroll
        for (int i = 0; i < 4; i++) {
            cpa16(st + soA[i], gA[i] + kb);
            cpa16(st + soB[i], gB[i] + kb);
        }
    };

#pragma unroll
    for (int p = 0; p < 2; p++) {
        if (p < nch) load_stage(p);
        cpa_commit();
    }

    const int lr = lid & 15, lc = lid >> 4;
    uint32_t offA[2], offB4[4];
#pragma unroll
    for (int m = 0; m < 2; m++) {
        int r = wm * 32 + m * 16 + lr;
        offA[m] = (uint32_t)(r * 128 + ((lc ^ (r & 7)) << 4));
    }
#pragma unroll
    for (int nb = 0; nb < 4; nb++) {
        int r = wn * 64 + nb * 16 + lr;
        offB4[nb] = (uint32_t)(16384 + r * 128 + ((lc ^ (r & 7)) << 4));
    }

    for (int ch = 0; ch < nch; ch++) {
        cpa_wait<1>();
        __syncthreads();
        if (ch + 2 < nch) load_stage(ch + 2);
        cpa_commit();

        const uint32_t st = sb + (ch % NSTAGE) * STAGE_B;
        uint32_t aH0 = st + offA[0], aH1 = st + offA[1];
        uint32_t aB0 = st + offB4[0], aB1 = st + offB4[1];
        uint32_t aB2 = st + offB4[2], aB3 = st + offB4[3];

#pragma unroll
        for (int ks = 0; ks < 4; ks++) {
            uint32_t ah[2][4], bq[4][4];
            ldm4(ah[0], aH0); ldm4(ah[1], aH1);
            ldm4(bq[0], aB0); ldm4(bq[1], aB1);
            ldm4(bq[2], aB2); ldm4(bq[3], aB3);
#pragma unroll
            for (int nb = 0; nb < 4; nb++)
#pragma unroll
                for (int m = 0; m < 2; m++) {
                    mma16(acc[m * 8 + 2 * nb],     ah[m], bq[nb][0], bq[nb][2]);
                    mma16(acc[m * 8 + 2 * nb + 1], ah[m], bq[nb][1], bq[nb][3]);
                }
            const uint32_t d = (ks & 1) ? 96u : 32u;
            aH0 ^= d; aH1 ^= d;
            aB0 ^= d; aB1 ^= d; aB2 ^= d; aB3 ^= d;
        }
    }

    const float* sE = (const float*)(smem + PARAM_B);
    const float* tE = (const float*)(smem + PARAM_B + 512);
    const int gid = lid >> 2, tp = lid & 3;

#pragma unroll
    for (int m = 0; m < 2; m++) {
#pragma unroll
        for (int t = 0; t < 4; t++) {
            const int ja = wn * 64 + t * 16 + tp * 2;
            const int jb = ja + 8;
            const int cn = g * 64 + (wn * 4 + t) * 8 + tp * 2;
            const float sa0 = sE[ja], sa1 = sE[ja + 1];
            const float ta0 = tE[ja], ta1 = tE[ja + 1];
            const float sb0 = sE[jb], sb1 = sE[jb + 1];
            const float tb0 = tE[jb], tb1 = tE[jb + 1];
            const float* ca = acc[m * 8 + 2 * t];
            const float* cb = acc[m * 8 + 2 * t + 1];
#pragma unroll
            for (int h = 0; h < 2; h++) {
                const int row = row0 + wm * 32 + m * 16 + gid + h * 8;
                float xa0 = ca[2 * h] * sa0 + ta0;
                float xa1 = ca[2 * h + 1] * sa1 + ta1;
                float xb0 = cb[2 * h] * sb0 + tb0;
                float xb1 = cb[2 * h + 1] * sb1 + tb1;
                float o0 = xa0 * (1.0f / (1.0f + __expf(-xb0)));
                float o1 = xa1 * (1.0f / (1.0f + __expf(-xb1)));
                const size_t ob = (size_t)row * HS + cn;
                __half2 hh;
                hh.x = __float2half_rn(o0);
                hh.y = __float2half_rn(o1);
                *(__half2*)(outh + ob) = hh;
            }
        }
    }
}

// ---------------- sparsemax: one warp per row (FIRST: prior starts at 1) -----
template<int FIRST>
__global__ __launch_bounds__(256)
void k_sparsemax(const float* __restrict__ z, float* __restrict__ prior,
                 float* __restrict__ maskOut, fp16* __restrict__ mf)
{
    const int row = blockIdx.x * 8 + (threadIdx.x >> 5);
    const int lid = threadIdx.x & 31;
    const size_t base = (size_t)row * 512;
    float v[16];
#pragma unroll
    for (int q = 0; q < 4; q++) {
        float4 t = *(const float4*)(z + base + q * 128 + lid * 4);
        v[q * 4 + 0] = t.x; v[q * 4 + 1] = t.y; v[q * 4 + 2] = t.z; v[q * 4 + 3] = t.w;
    }
    float zmax = v[0];
#pragma unroll
    for (int i = 1; i < 16; i++) zmax = fmaxf(zmax, v[i]);
#pragma unroll
    for (int o = 16; o; o >>= 1) zmax = fmaxf(zmax, __shfl_xor_sync(0xffffffffu, zmax, o));

    float lo = zmax - 1.0f, hi = zmax;
    for (int it = 0; it < 20; it++) {
        float mid = 0.5f * (lo + hi);
        float s = 0.0f;
#pragma unroll
        for (int i = 0; i < 16; i++) s += fmaxf(v[i] - mid, 0.0f);
#pragma unroll
        for (int o = 16; o; o >>= 1) s += __shfl_xor_sync(0xffffffffu, s, o);
        if (s >= 1.0f) lo = mid; else hi = mid;
    }
    float sum = 0.0f, cnt = 0.0f;
#pragma unroll
    for (int i = 0; i < 16; i++) {
        if (v[i] > lo) { sum += v[i]; cnt += 1.0f; }
    }
#pragma unroll
    for (int o = 16; o; o >>= 1) {
        sum += __shfl_xor_sync(0xffffffffu, sum, o);
        cnt += __shfl_xor_sync(0xffffffffu, cnt, o);
    }
    const float tau = (sum - 1.0f) / cnt;

#pragma unroll
    for (int q = 0; q < 4; q++) {
        const size_t off = base + q * 128 + lid * 4;
        float4 mk;
        mk.x = fmaxf(v[q * 4 + 0] - tau, 0.0f);
        mk.y = fmaxf(v[q * 4 + 1] - tau, 0.0f);
        mk.z = fmaxf(v[q * 4 + 2] - tau, 0.0f);
        mk.w = fmaxf(v[q * 4 + 3] - tau, 0.0f);
        *(float4*)(maskOut + off) = mk;
        float4 pr;
        if (FIRST) {
            pr.x = 1.5f - mk.x; pr.y = 1.5f - mk.y;
            pr.z = 1.5f - mk.z; pr.w = 1.5f - mk.w;
        } else {
            pr = *(const float4*)(prior + off);
            pr.x *= (1.5f - mk.x); pr.y *= (1.5f - mk.y);
            pr.z *= (1.5f - mk.z); pr.w *= (1.5f - mk.w);
        }
        *(float4*)(prior + off) = pr;
        __half2 f01 = *(const __half2*)(g_featsh + off);
        __half2 f23 = *(const __half2*)(g_featsh + off + 2);
        __half2 p0, p1;
        p0.x = __float2half_rn(mk.x * __half2float(f01.x));
        p0.y = __float2half_rn(mk.y * __half2float(f01.y));
        p1.x = __float2half_rn(mk.z * __half2float(f23.x));
        p1.y = __float2half_rn(mk.w * __half2float(f23.y));
        *(__half2*)(mf + off) = p0;
        *(__half2*)(mf + off + 2) = p1;
    }
}

// ---------------- final projection ----------------
__global__ __launch_bounds__(256)
void k_fin(const float* __restrict__ A, const float* __restrict__ W,
           const float* __restrict__ bias, float* __restrict__ C)
{
    __shared__ float As[16][128];
    __shared__ float Ws[16][64];
    const int tid = threadIdx.x;
    const int ty = tid >> 4, tx = tid & 15;
    const int row0 = blockIdx.y * 128;
    const int col0 = blockIdx.x * 64;

    float acc[8][4];
#pragma unroll
    for (int r = 0; r < 8; r++)
#pragma unroll
        for (int c = 0; c < 4; c++) acc[r][c] = 0.f;

    for (int kt = 0; kt < 128; kt += 16) {
#pragma unroll
        for (int l = 0; l < 2; l++) {
            int li = tid * 2 + l;
            int r = li >> 2, kq = (li & 3) * 4;
            float4 av = *(const float4*)(A + (size_t)(row0 + r) * 128 + kt + kq);
            As[kq + 0][r] = av.x; As[kq + 1][r] = av.y;
            As[kq + 2][r] = av.z; As[kq + 3][r] = av.w;
        }
        *(float4*)&Ws[tid >> 4][(tid & 15) * 4] =
            *(const float4*)(W + (size_t)(kt + (tid >> 4)) * 128 + col0 + (tid & 15) * 4);
        __syncthreads();
#pragma unroll
        for (int kk = 0; kk < 16; kk++) {
            float a[8];
            float4 a0 = *(float4*)&As[kk][ty * 8];
            float4 a1 = *(float4*)&As[kk][ty * 8 + 4];
            a[0] = a0.x; a[1] = a0.y; a[2] = a0.z; a[3] = a0.w;
            a[4] = a1.x; a[5] = a1.y; a[6] = a1.z; a[7] = a1.w;
            float4 w0 = *(float4*)&Ws[kk][tx * 4];
            float wv[4] = {w0.x, w0.y, w0.z, w0.w};
#pragma unroll
            for (int r = 0; r < 8; r++)
#pragma unroll
                for (int c = 0; c < 4; c++) acc[r][c] += a[r] * wv[c];
        }
        __syncthreads();
    }
#pragma unroll
    for (int r = 0; r < 8; r++) {
        int gr = row0 + ty * 8 + r;
#pragma unroll
        for (int c = 0; c < 4; c++) {
            int gc = col0 + tx * 4 + c;
            C[(size_t)gr * 128 + gc] = acc[r][c] + bias[gc];
        }
    }
}

// ---------------- launch ----------------
extern "C" void kernel_launch(void* const* d_in, const int* in_sizes, int n_in,
                              void* d_out, int out_size)
{
    const float* features = (const float*)d_in[0];
    const float* bn0_g = (const float*)d_in[1];
    const float* bn0_b = (const float*)d_in[2];
    const float* bn0_m = (const float*)d_in[3];
    const float* bn0_v = (const float*)d_in[4];
    const float* Ws0   = (const float*)d_in[5];
    const float* Ws1   = (const float*)d_in[6];
    const float* Wu    = (const float*)d_in[7];
    const float* ft_g  = (const float*)d_in[8];
    const float* ft_b  = (const float*)d_in[9];
    const float* ft_m  = (const float*)d_in[10];
    const float* ft_v  = (const float*)d_in[11];
    const float* W_att = (const float*)d_in[12];
    const float* att_g = (const float*)d_in[13];
    const float* att_b = (const float*)d_in[14];
    const float* att_m = (const float*)d_in[15];
    const float* att_v = (const float*)d_in[16];
    const float* Wf    = (const float*)d_in[17];
    const float* bf    = (const float*)d_in[18];

    float *zp, *prior, *acc;
    fp16 *A, *h0, *h1;
    fp16 *W0, *W1, *WU, *WA;
    float *fts, *ftt, *as, *at;
    cudaGetSymbolAddress((void**)&A, g_A);
    cudaGetSymbolAddress((void**)&h0, g_h0);
    cudaGetSymbolAddress((void**)&h1, g_h1);
    cudaGetSymbolAddress((void**)&zp, g_z);
    cudaGetSymbolAddress((void**)&prior, g_prior);
    cudaGetSymbolAddress((void**)&acc, g_acc);
    cudaGetSymbolAddress((void**)&W0, g_W0);
    cudaGetSymbolAddress((void**)&W1, g_W1);
    cudaGetSymbolAddress((void**)&WU, g_WU);
    cudaGetSymbolAddress((void**)&WA, g_WA);
    cudaGetSymbolAddress((void**)&fts, g_fts);
    cudaGetSymbolAddress((void**)&ftt, g_ftt);
    cudaGetSymbolAddress((void**)&as, g_as);
    cudaGetSymbolAddress((void**)&at, g_at);

    float* outF  = (float*)d_out;
    float* masks = outF + (size_t)BATCH * OUTD;

    static bool attr_set = false;
    if (!attr_set) {
        cudaFuncSetAttribute(k_mma_s<0, 0>, cudaFuncAttributeMaxDynamicSharedMemorySize, SMEM_S);
        cudaFuncSetAttribute(k_mma_s<1, 0>, cudaFuncAttributeMaxDynamicSharedMemorySize, SMEM_S);
        cudaFuncSetAttribute(k_mma_s<1, 1>, cudaFuncAttributeMaxDynamicSharedMemorySize, SMEM_S);
        cudaFuncSetAttribute(k_mma_b, cudaFuncAttributeMaxDynamicSharedMemorySize, SMEM_B);
        attr_set = true;
    }

    // fused setup: weight/bn prep + bn0 init, one launch
    k_setup<<<SETUP_BLK, 256>>>(features, bn0_g, bn0_b, bn0_m, bn0_v,
                                Ws0, Ws1, Wu, W_att,
                                ft_g, ft_b, ft_m, ft_v,
                                att_g, att_b, att_m, att_v);

    const dim3 gS(4, BATCH / 64);
    const dim3 gB(4, BATCH / 128);

    auto ft_transformer = [&](int t, float* accOut) {
        const float* s0 = fts + (size_t)t * 4 * 512;
        const float* t0 = ftt + (size_t)t * 4 * 512;
        k_mma_b<<<gB, 256, SMEM_B>>>(A, 512, 512, W0, s0, t0, h0);
        k_mma_s<0, 0><<<gS, 256, SMEM_S>>>(h0, 256, 256, W1,
            s0 + 512, t0 + 512, h0, h1, nullptr, nullptr, nullptr);
        k_mma_s<0, 0><<<gS, 256, SMEM_S>>>(h1, 256, 256,
            WU + (size_t)(t * 2 + 0) * 512 * 256,
            s0 + 1024, t0 + 1024, h1, h0, nullptr, nullptr, nullptr);
        k_mma_s<0, 0><<<gS, 256, SMEM_S>>>(h0, 256, 256,
            WU + (size_t)(t * 2 + 1) * 512 * 256,
            s0 + 1536, t0 + 1536, h0, h1, accOut, nullptr, nullptr);
    };

    ft_transformer(0, nullptr);

    for (int s = 0; s < STEPS; s++) {
        if (s == 0) {
            k_mma_s<1, 0><<<gS, 256, SMEM_S>>>(h1 + 128, 256, 128,
                WA, as, at, nullptr, nullptr, nullptr, nullptr, zp);
            k_sparsemax<1><<<BATCH / 8, 256>>>(zp, prior, masks, A);
        } else {
            k_mma_s<1, 1><<<gS, 256, SMEM_S>>>(h1 + 128, 256, 128,
                WA + (size_t)s * 512 * 128,
                as + (size_t)s * 512, at + (size_t)s * 512,
                nullptr, nullptr, nullptr,
                prior, zp);
            k_sparsemax<0><<<BATCH / 8, 256>>>(zp, prior,
                masks + (size_t)s * BATCH * FDIM, A);
        }
        ft_transformer(s + 1, acc);
    }

    k_fin<<<dim3(2, BATCH / 128), 256>>>(acc, Wf, bf, outF);
}

// round 16
// speedup vs baseline: 1.2615x; 1.0789x over previous
#include <cuda_runtime.h>
#include <cuda_fp16.h>
#include <math.h>
#include <stdint.h>

#define BATCH 32768
#define FDIM 512
#define HS 256
#define OUTD 128
#define STEPS 5
#define EPSBN 1e-5f

typedef __half fp16;

// ---------------- scratch (device globals; no allocation) ----------------
__device__ fp16  g_featsh[BATCH * FDIM];
__device__ fp16  g_A[BATCH * FDIM];
__device__ fp16  g_h0[BATCH * HS];
__device__ fp16  g_h1[BATCH * HS];
__device__ float g_z[BATCH * FDIM];
__device__ float g_prior[BATCH * FDIM];
__device__ float g_acc[BATCH * OUTD];

// prepped weights ([N,K] fp16; GLU ones N-permuted with 8-col a/b interleave)
__device__ fp16 g_W0[512 * 512];
__device__ fp16 g_W1[512 * 256];
__device__ fp16 g_WU[12 * 512 * 256];
__device__ fp16 g_WA[5 * 512 * 128];
__device__ float g_fts[6 * 4 * 512], g_ftt[6 * 4 * 512];
__device__ float g_as[5 * 512], g_at[5 * 512];

// ---------------- PTX helpers ----------------
__device__ __forceinline__ uint32_t smem_u32(const void* p) {
    uint32_t a;
    asm("{ .reg .u64 t; cvta.to.shared.u64 t, %1; cvt.u32.u64 %0, t; }" : "=r"(a) : "l"(p));
    return a;
}
__device__ __forceinline__ void cpa16(uint32_t s, const void* g) {
    asm volatile("cp.async.cg.shared.global [%0], [%1], 16;" :: "r"(s), "l"(g));
}
__device__ __forceinline__ void cpa_commit() {
    asm volatile("cp.async.commit_group;" ::: "memory");
}
template<int N>
__device__ __forceinline__ void cpa_wait() {
    asm volatile("cp.async.wait_group %0;" :: "n"(N) : "memory");
}
__device__ __forceinline__ void ldm4(uint32_t* v, uint32_t addr) {
    asm volatile("ldmatrix.sync.aligned.m8n8.x4.shared.b16 {%0,%1,%2,%3}, [%4];"
                 : "=r"(v[0]), "=r"(v[1]), "=r"(v[2]), "=r"(v[3]) : "r"(addr));
}
__device__ __forceinline__ void mma16(float* c, const uint32_t* a, uint32_t b0, uint32_t b1) {
    asm("mma.sync.aligned.m16n8k16.row.col.f32.f16.f16.f32 "
        "{%0,%1,%2,%3}, {%4,%5,%6,%7}, {%8,%9}, {%0,%1,%2,%3};"
        : "+f"(c[0]), "+f"(c[1]), "+f"(c[2]), "+f"(c[3])
        : "r"(a[0]), "r"(a[1]), "r"(a[2]), "r"(a[3]), "r"(b0), "r"(b1));
}

// ---------------- fused setup: init + tiled-transpose weight prep + bn ------
// INIT: 4 elems/thread, vectorized.
#define INIT2_BLK (BATCH * FDIM / 1024)     // 16384
// Transpose tiles: 64(k) x 64(n) per block.
#define T_W0 64                             // 8 kt x 8 nt
#define T_W1 32                             // 4 kt x 8 nt
#define T_WU (12 * 32)                      // 384
#define T_WA (5 * 16)                       // 80 (2 kt x 8 nt per step)
#define T_TILES (T_W0 + T_W1 + T_WU + T_WA) // 560
#define BN_BLK 48
#define SETUP_BLK (INIT2_BLK + T_TILES + BN_BLK)

__global__ void k_setup(const float* __restrict__ feat,
                        const float* __restrict__ g0, const float* __restrict__ b0,
                        const float* __restrict__ m0, const float* __restrict__ v0,
                        const float* __restrict__ Ws0,
                        const float* __restrict__ Ws1,
                        const float* __restrict__ Wu,
                        const float* __restrict__ Wa,
                        const float* __restrict__ fg, const float* __restrict__ fb,
                        const float* __restrict__ fm, const float* __restrict__ fv,
                        const float* __restrict__ ag, const float* __restrict__ ab,
                        const float* __restrict__ am, const float* __restrict__ av)
{
    __shared__ float tile[64][65];
    const int b = blockIdx.x;
    const int t = threadIdx.x;

    if (b < INIT2_BLK) {
        const int base = (b * 256 + t) * 4;
        const int c = base & (FDIM - 1);
        float4 f = *(const float4*)(feat + base);
        float4 gg = *(const float4*)(g0 + c);
        float4 bb = *(const float4*)(b0 + c);
        float4 mm = *(const float4*)(m0 + c);
        float4 vv = *(const float4*)(v0 + c);
        float o0 = gg.x * (f.x - mm.x) * rsqrtf(vv.x + EPSBN) + bb.x;
        float o1 = gg.y * (f.y - mm.y) * rsqrtf(vv.y + EPSBN) + bb.y;
        float o2 = gg.z * (f.z - mm.z) * rsqrtf(vv.z + EPSBN) + bb.z;
        float o3 = gg.w * (f.w - mm.w) * rsqrtf(vv.w + EPSBN) + bb.w;
        __half2 h01, h23;
        h01.x = __float2half_rn(o0); h01.y = __float2half_rn(o1);
        h23.x = __float2half_rn(o2); h23.y = __float2half_rn(o3);
        *(__half2*)(g_featsh + base) = h01;
        *(__half2*)(g_featsh + base + 2) = h23;
        *(__half2*)(g_A + base) = h01;
        *(__half2*)(g_A + base + 2) = h23;
        if (base < BATCH * OUTD) {
            float4 z4 = {0.f, 0.f, 0.f, 0.f};
            *(float4*)(g_acc + base) = z4;
        }
        return;
    }
    if (b < INIT2_BLK + T_TILES) {
        int r = b - INIT2_BLK;
        const float* src;
        fp16* dst;
        int K, kt, nt, perm;
        if (r < T_W0) {
            src = Ws0; dst = g_W0; K = 512; perm = 1;
            kt = (r >> 3) * 64; nt = (r & 7) * 64;
        } else if (r < T_W0 + T_W1) {
            r -= T_W0;
            src = Ws1; dst = g_W1; K = 256; perm = 1;
            kt = (r >> 3) * 64; nt = (r & 7) * 64;
        } else if (r < T_W0 + T_W1 + T_WU) {
            r -= T_W0 + T_W1;
            int mi = r >> 5, rr = r & 31;
            src = Wu + (size_t)mi * 256 * 512;
            dst = g_WU + (size_t)mi * 512 * 256;
            K = 256; perm = 1;
            kt = (rr >> 3) * 64; nt = (rr & 7) * 64;
        } else {
            r -= T_W0 + T_W1 + T_WU;
            int si = r >> 4, rr = r & 15;
            src = Wa + (size_t)si * 128 * 512;
            dst = g_WA + (size_t)si * 512 * 128;
            K = 128; perm = 0;
            kt = (rr >> 3) * 64; nt = (rr & 7) * 64;
        }
        const int c0 = nt >> 1;
#pragma unroll
        for (int i = 0; i < 16; i++) {
            int lin = i * 256 + t;
            int rr2 = lin >> 6, cc = lin & 63;
            int col = perm ? ((cc < 32) ? (c0 + cc) : (256 + c0 + cc - 32)) : (nt + cc);
            tile[rr2][cc] = src[(size_t)(kt + rr2) * 512 + col];
        }
        __syncthreads();
#pragma unroll
        for (int i = 0; i < 16; i++) {
            int lin = i * 256 + t;
            int dn = lin >> 6, dk = lin & 63;
            int cc;
            if (perm) {
                int half = (dn >> 3) & 1, jl = dn & 7, qq = dn >> 4;
                cc = half * 32 + qq * 8 + jl;
            } else {
                cc = dn;
            }
            dst[(size_t)(nt + dn) * K + kt + dk] = __float2half_rn(tile[dk][cc]);
        }
        return;
    }
    {
        int idx = (b - INIT2_BLK - T_TILES) * 256 + t;
        if (idx < 6 * 4 * 512) {
            float s = fg[idx] * rsqrtf(fv[idx] + EPSBN);
            g_fts[idx] = s;
            g_ftt[idx] = fb[idx] - fm[idx] * s;
        }
        if (idx < 5 * 512) {
            float s = ag[idx] * rsqrtf(av[idx] + EPSBN);
            g_as[idx] = s;
            g_at[idx] = ab[idx] - am[idx] * s;
        }
    }
}

// ================= small-tile GEMM: MODE 0 GLU / MODE 1 att (PR: use prior) ==
// 256 threads, 3 CTAs/SM. BM=64, BN=128, BK=64. Warp grid 2(M)x4(N), tile 32x32.
#define STAGE_S 24576     // A 8K | B 16K
#define NSTAGE 3
#define PARAM_S (NSTAGE * STAGE_S)
#define SMEM_S  (PARAM_S + 1024)

template<int MODE, int PR>
__global__ __launch_bounds__(256, 3)
void k_mma_s(const fp16* __restrict__ A, int lda, int K,
             const fp16* __restrict__ B,
             const float* __restrict__ bs, const float* __restrict__ bt,
             const fp16* __restrict__ resh,
             fp16* __restrict__ outh,
             float* __restrict__ accp,
             const float* __restrict__ prior, float* __restrict__ zout)
{
    extern __shared__ __align__(128) char smem[];
    const int tid = threadIdx.x, wid = tid >> 5, lid = tid & 31;
    const int wm = wid >> 2, wn = wid & 3;
    const int g = blockIdx.x;
    const int row0 = blockIdx.y * 64;
    const uint32_t sb = smem_u32(smem);

    if (tid < 128) {
        float* sE = (float*)(smem + PARAM_S);
        float* tE = (float*)(smem + PARAM_S + 512);
        int col;
        if (MODE == 0) {
            int q2 = tid >> 4, rr = tid & 15, half = rr >> 3, jl = rr & 7;
            col = (half ? 256 : 0) + g * 64 + q2 * 8 + jl;
        } else {
            col = g * 128 + tid;
        }
        sE[tid] = bs[col];
        tE[tid] = bt[col];
    }

    float acc[8][4];
#pragma unroll
    for (int i = 0; i < 8; i++)
#pragma unroll
        for (int j = 0; j < 4; j++) acc[i][j] = 0.0f;

    const int nch = K >> 6;

    const char* gA[2];
    const char* gB[4];
    uint32_t soA[2], soB[4];
#pragma unroll
    for (int i = 0; i < 2; i++) {
        int idx = tid + i * 256;
        int r = idx >> 3, c = idx & 7;
        soA[i] = (uint32_t)(r * 128 + ((c ^ (r & 7)) << 4));
        gA[i] = (const char*)(A + (size_t)(row0 + r) * lda + c * 8);
    }
#pragma unroll
    for (int i = 0; i < 4; i++) {
        int idx = tid + i * 256;
        int r = idx >> 3, c = idx & 7;
        soB[i] = (uint32_t)(8192 + r * 128 + ((c ^ (r & 7)) << 4));
        gB[i] = (const char*)(B + (size_t)(g * 128 + r) * K + c * 8);
    }

    auto load_stage = [&](int ch) {
        const uint32_t st = sb + (ch % NSTAGE) * STAGE_S;
        const int kb = ch << 7;
#pragma unroll
        for (int i = 0; i < 2; i++) cpa16(st + soA[i], gA[i] + kb);
#pragma unroll
        for (int i = 0; i < 4; i++) cpa16(st + soB[i], gB[i] + kb);
    };

#pragma unroll
    for (int p = 0; p < 2; p++) {
        if (p < nch) load_stage(p);
        cpa_commit();
    }

    const int lr = lid & 15, lc = lid >> 4;
    uint32_t offA[2], offB2[2];
#pragma unroll
    for (int m = 0; m < 2; m++) {
        int r = wm * 32 + m * 16 + lr;
        offA[m] = (uint32_t)(r * 128 + ((lc ^ (r & 7)) << 4));
    }
#pragma unroll
    for (int q = 0; q < 2; q++) {
        int r = wn * 32 + q * 16 + lr;
        offB2[q] = (uint32_t)(8192 + r * 128 + ((lc ^ (r & 7)) << 4));
    }

    for (int ch = 0; ch < nch; ch++) {
        cpa_wait<1>();
        __syncthreads();
        if (ch + 2 < nch) load_stage(ch + 2);
        cpa_commit();

        const uint32_t st = sb + (ch % NSTAGE) * STAGE_S;
        uint32_t aH0 = st + offA[0], aH1 = st + offA[1];
        uint32_t aB0 = st + offB2[0], aB1 = st + offB2[1];

#pragma unroll
        for (int ks = 0; ks < 4; ks++) {
            uint32_t ah[2][4], bq[2][4];
            ldm4(ah[0], aH0); ldm4(ah[1], aH1);
            ldm4(bq[0], aB0); ldm4(bq[1], aB1);
#pragma unroll
            for (int m = 0; m < 2; m++) {
                mma16(acc[m * 4 + 0], ah[m], bq[0][0], bq[0][2]);
                mma16(acc[m * 4 + 1], ah[m], bq[0][1], bq[0][3]);
                mma16(acc[m * 4 + 2], ah[m], bq[1][0], bq[1][2]);
                mma16(acc[m * 4 + 3], ah[m], bq[1][1], bq[1][3]);
            }
            const uint32_t d = (ks & 1) ? 96u : 32u;
            aH0 ^= d; aH1 ^= d;
            aB0 ^= d; aB1 ^= d;
        }
    }

    const float* sE = (const float*)(smem + PARAM_S);
    const float* tE = (const float*)(smem + PARAM_S + 512);
    const int gid = lid >> 2, tp = lid & 3;

    if (MODE == 0) {
#pragma unroll
        for (int m = 0; m < 2; m++) {
#pragma unroll
            for (int t = 0; t < 2; t++) {
                const int ja = wn * 32 + t * 16 + tp * 2;
                const int jb = ja + 8;
                const int cn = g * 64 + (wn * 2 + t) * 8 + tp * 2;
                const float sa0 = sE[ja], sa1 = sE[ja + 1];
                const float ta0 = tE[ja], ta1 = tE[ja + 1];
                const float sb0 = sE[jb], sb1 = sE[jb + 1];
                const float tb0 = tE[jb], tb1 = tE[jb + 1];
                const float* ca = acc[m * 4 + 2 * t];
                const float* cb = acc[m * 4 + 2 * t + 1];
#pragma unroll
                for (int h = 0; h < 2; h++) {
                    const int row = row0 + wm * 32 + m * 16 + gid + h * 8;
                    float xa0 = ca[2 * h] * sa0 + ta0;
                    float xa1 = ca[2 * h + 1] * sa1 + ta1;
                    float xb0 = cb[2 * h] * sb0 + tb0;
                    float xb1 = cb[2 * h + 1] * sb1 + tb1;
                    float o0 = __fdividef(xa0, 1.0f + __expf(-xb0));
                    float o1 = __fdividef(xa1, 1.0f + __expf(-xb1));
                    const size_t ob = (size_t)row * HS + cn;
                    if (resh) {
                        __half2 rh = *(const __half2*)(resh + ob);
                        o0 = fmaf(__half2float(rh.x), 0.70710678118654752f, o0);
                        o1 = fmaf(__half2float(rh.y), 0.70710678118654752f, o1);
                    }
                    __half2 hh;
                    hh.x = __float2half_rn(o0);
                    hh.y = __float2half_rn(o1);
                    *(__half2*)(outh + ob) = hh;
                    if (accp && g < 2) {
                        float2* ap = (float2*)(accp + (size_t)row * OUTD + cn);
                        float2 av = *ap;
                        av.x += fmaxf(o0, 0.0f);
                        av.y += fmaxf(o1, 0.0f);
                        *ap = av;
                    }
                }
            }
        }
    } else {
#pragma unroll
        for (int m = 0; m < 2; m++) {
#pragma unroll
            for (int nb = 0; nb < 4; nb++) {
                const int cn = wn * 32 + nb * 8 + tp * 2;
                const float s0 = sE[cn], s1 = sE[cn + 1];
                const float t0 = tE[cn], t1 = tE[cn + 1];
                const float* ca = acc[m * 4 + nb];
#pragma unroll
                for (int h = 0; h < 2; h++) {
                    const int row = row0 + wm * 32 + m * 16 + gid + h * 8;
                    const size_t idx = (size_t)row * FDIM + g * 128 + cn;
                    float2 zz;
                    zz.x = ca[2 * h] * s0 + t0;
                    zz.y = ca[2 * h + 1] * s1 + t1;
                    if (PR) {
                        float2 pr = *(const float2*)(prior + idx);
                        zz.x *= pr.x;
                        zz.y *= pr.y;
                    }
                    *(float2*)(zout + idx) = zz;
                }
            }
        }
    }
}

// ================= big-tile GEMM for K=512 block-0 ==========================
// 256 threads, 2 CTAs/SM. BM=128, BN=128, BK=64. Warp grid 4(M)x2(N), tile 32x64.
#define STAGE_B 32768     // A 16K | B 16K
#define PARAM_B (NSTAGE * STAGE_B)
#define SMEM_B  (PARAM_B + 1024)

__global__ __launch_bounds__(256, 2)
void k_mma_b(const fp16* __restrict__ A, int lda, int K,
             const fp16* __restrict__ B,
             const float* __restrict__ bs, const float* __restrict__ bt,
             fp16* __restrict__ outh)
{
    extern __shared__ __align__(128) char smem[];
    const int tid = threadIdx.x, wid = tid >> 5, lid = tid & 31;
    const int wm = wid >> 1, wn = wid & 1;
    const int g = blockIdx.x;
    const int row0 = blockIdx.y * 128;
    const uint32_t sb = smem_u32(smem);

    if (tid < 128) {
        float* sE = (float*)(smem + PARAM_B);
        float* tE = (float*)(smem + PARAM_B + 512);
        int q2 = tid >> 4, rr = tid & 15, half = rr >> 3, jl = rr & 7;
        int col = (half ? 256 : 0) + g * 64 + q2 * 8 + jl;
        sE[tid] = bs[col];
        tE[tid] = bt[col];
    }

    float acc[16][4];
#pragma unroll
    for (int i = 0; i < 16; i++)
#pragma unroll
        for (int j = 0; j < 4; j++) acc[i][j] = 0.0f;

    const int nch = K >> 6;

    const char* gA[4];
    const char* gB[4];
    uint32_t soA[4], soB[4];
#pragma unroll
    for (int i = 0; i < 4; i++) {
        int idx = tid + i * 256;
        int r = idx >> 3, c = idx & 7;
        uint32_t so = (uint32_t)(r * 128 + ((c ^ (r & 7)) << 4));
        soA[i] = so;
        soB[i] = 16384u + so;
        gA[i] = (const char*)(A + (size_t)(row0 + r) * lda + c * 8);
        gB[i] = (const char*)(B + (size_t)(g * 128 + r) * K + c * 8);
    }

    auto load_stage = [&](int ch) {
        const uint32_t st = sb + (ch % NSTAGE) * STAGE_B;
        const int kb = ch << 7;
#pragma unroll
        for (int i = 0; i < 4; i++) {
            cpa16(st + soA[i], gA[i] + kb);
            cpa16(st + soB[i], gB[i] + kb);
        }
    };

#pragma unroll
    for (int p = 0; p < 2; p++) {
        if (p < nch) load_stage(p);
        cpa_commit();
    }

    const int lr = lid & 15, lc = lid >> 4;
    uint32_t offA[2], offB4[4];
#pragma unroll
    for (int m = 0; m < 2; m++) {
        int r = wm * 32 + m * 16 + lr;
        offA[m] = (uint32_t)(r * 128 + ((lc ^ (r & 7)) << 4));
    }
#pragma unroll
    for (int nb = 0; nb < 4; nb++) {
        int r = wn * 64 + nb * 16 + lr;
        offB4[nb] = (uint32_t)(16384 + r * 128 + ((lc ^ (r & 7)) << 4));
    }

    for (int ch = 0; ch < nch; ch++) {
        cpa_wait<1>();
        __syncthreads();
        if (ch + 2 < nch) load_stage(ch + 2);
        cpa_commit();

        const uint32_t st = sb + (ch % NSTAGE) * STAGE_B;
        uint32_t aH0 = st + offA[0], aH1 = st + offA[1];
        uint32_t aB0 = st + offB4[0], aB1 = st + offB4[1];
        uint32_t aB2 = st + offB4[2], aB3 = st + offB4[3];

#pragma unroll
        for (int ks = 0; ks < 4; ks++) {
            uint32_t ah[2][4], bq[4][4];
            ldm4(ah[0], aH0); ldm4(ah[1], aH1);
            ldm4(bq[0], aB0); ldm4(bq[1], aB1);
            ldm4(bq[2], aB2); ldm4(bq[3], aB3);
#pragma unroll
            for (int nb = 0; nb < 4; nb++)
#pragma unroll
                for (int m = 0; m < 2; m++) {
                    mma16(acc[m * 8 + 2 * nb],     ah[m], bq[nb][0], bq[nb][2]);
                    mma16(acc[m * 8 + 2 * nb + 1], ah[m], bq[nb][1], bq[nb][3]);
                }
            const uint32_t d = (ks & 1) ? 96u : 32u;
            aH0 ^= d; aH1 ^= d;
            aB0 ^= d; aB1 ^= d; aB2 ^= d; aB3 ^= d;
        }
    }

    const float* sE = (const float*)(smem + PARAM_B);
    const float* tE = (const float*)(smem + PARAM_B + 512);
    const int gid = lid >> 2, tp = lid & 3;

#pragma unroll
    for (int m = 0; m < 2; m++) {
#pragma unroll
        for (int t = 0; t < 4; t++) {
            const int ja = wn * 64 + t * 16 + tp * 2;
            const int jb = ja + 8;
            const int cn = g * 64 + (wn * 4 + t) * 8 + tp * 2;
            const float sa0 = sE[ja], sa1 = sE[ja + 1];
            const float ta0 = tE[ja], ta1 = tE[ja + 1];
            const float sb0 = sE[jb], sb1 = sE[jb + 1];
            const float tb0 = tE[jb], tb1 = tE[jb + 1];
            const float* ca = acc[m * 8 + 2 * t];
            const float* cb = acc[m * 8 + 2 * t + 1];
#pragma unroll
            for (int h = 0; h < 2; h++) {
                const int row = row0 + wm * 32 + m * 16 + gid + h * 8;
                float xa0 = ca[2 * h] * sa0 + ta0;
                float xa1 = ca[2 * h + 1] * sa1 + ta1;
                float xb0 = cb[2 * h] * sb0 + tb0;
                float xb1 = cb[2 * h + 1] * sb1 + tb1;
                float o0 = __fdividef(xa0, 1.0f + __expf(-xb0));
                float o1 = __fdividef(xa1, 1.0f + __expf(-xb1));
                const size_t ob = (size_t)row * HS + cn;
                __half2 hh;
                hh.x = __float2half_rn(o0);
                hh.y = __float2half_rn(o1);
                *(__half2*)(outh + ob) = hh;
            }
        }
    }
}

// ---------------- sparsemax: one warp per row (FIRST: prior starts at 1) -----
template<int FIRST>
__global__ __launch_bounds__(256)
void k_sparsemax(const float* __restrict__ z, float* __restrict__ prior,
                 float* __restrict__ maskOut, fp16* __restrict__ mf)
{
    const int row = blockIdx.x * 8 + (threadIdx.x >> 5);
    const int lid = threadIdx.x & 31;
    const size_t base = (size_t)row * 512;
    float v[16];
#pragma unroll
    for (int q = 0; q < 4; q++) {
        float4 t = *(const float4*)(z + base + q * 128 + lid * 4);
        v[q * 4 + 0] = t.x; v[q * 4 + 1] = t.y; v[q * 4 + 2] = t.z; v[q * 4 + 3] = t.w;
    }
    float zmax = v[0];
#pragma unroll
    for (int i = 1; i < 16; i++) zmax = fmaxf(zmax, v[i]);
#pragma unroll
    for (int o = 16; o; o >>= 1) zmax = fmaxf(zmax, __shfl_xor_sync(0xffffffffu, zmax, o));

    float lo = zmax - 1.0f, hi = zmax;
    for (int it = 0; it < 20; it++) {
        float mid = 0.5f * (lo + hi);
        float s = 0.0f;
#pragma unroll
        for (int i = 0; i < 16; i++) s += fmaxf(v[i] - mid, 0.0f);
#pragma unroll
        for (int o = 16; o; o >>= 1) s += __shfl_xor_sync(0xffffffffu, s, o);
        if (s >= 1.0f) lo = mid; else hi = mid;
    }
    float sum = 0.0f, cnt = 0.0f;
#pragma unroll
    for (int i = 0; i < 16; i++) {
        if (v[i] > lo) { sum += v[i]; cnt += 1.0f; }
    }
#pragma unroll
    for (int o = 16; o; o >>= 1) {
        sum += __shfl_xor_sync(0xffffffffu, sum, o);
        cnt += __shfl_xor_sync(0xffffffffu, cnt, o);
    }
    const float tau = (sum - 1.0f) / cnt;

#pragma unroll
    for (int q = 0; q < 4; q++) {
        const size_t off = base + q * 128 + lid * 4;
        float4 mk;
        mk.x = fmaxf(v[q * 4 + 0] - tau, 0.0f);
        mk.y = fmaxf(v[q * 4 + 1] - tau, 0.0f);
        mk.z = fmaxf(v[q * 4 + 2] - tau, 0.0f);
        mk.w = fmaxf(v[q * 4 + 3] - tau, 0.0f);
        *(float4*)(maskOut + off) = mk;
        float4 pr;
        if (FIRST) {
            pr.x = 1.5f - mk.x; pr.y = 1.5f - mk.y;
            pr.z = 1.5f - mk.z; pr.w = 1.5f - mk.w;
        } else {
            pr = *(const float4*)(prior + off);
            pr.x *= (1.5f - mk.x); pr.y *= (1.5f - mk.y);
            pr.z *= (1.5f - mk.z); pr.w *= (1.5f - mk.w);
        }
        *(float4*)(prior + off) = pr;
        __half2 f01 = *(const __half2*)(g_featsh + off);
        __half2 f23 = *(const __half2*)(g_featsh + off + 2);
        __half2 p0, p1;
        p0.x = __float2half_rn(mk.x * __half2float(f01.x));
        p0.y = __float2half_rn(mk.y * __half2float(f01.y));
        p1.x = __float2half_rn(mk.z * __half2float(f23.x));
        p1.y = __float2half_rn(mk.w * __half2float(f23.y));
        *(__half2*)(mf + off) = p0;
        *(__half2*)(mf + off + 2) = p1;
    }
}

// ---------------- final projection ----------------
__global__ __launch_bounds__(256)
void k_fin(const float* __restrict__ A, const float* __restrict__ W,
           const float* __restrict__ bias, float* __restrict__ C)
{
    __shared__ float As[16][128];
    __shared__ float Ws[16][64];
    const int tid = threadIdx.x;
    const int ty = tid >> 4, tx = tid & 15;
    const int row0 = blockIdx.y * 128;
    const int col0 = blockIdx.x * 64;

    float acc[8][4];
#pragma unroll
    for (int r = 0; r < 8; r++)
#pragma unroll
        for (int c = 0; c < 4; c++) acc[r][c] = 0.f;

    for (int kt = 0; kt < 128; kt += 16) {
#pragma unroll
        for (int l = 0; l < 2; l++) {
            int li = tid * 2 + l;
            int r = li >> 2, kq = (li & 3) * 4;
            float4 av = *(const float4*)(A + (size_t)(row0 + r) * 128 + kt + kq);
            As[kq + 0][r] = av.x; As[kq + 1][r] = av.y;
            As[kq + 2][r] = av.z; As[kq + 3][r] = av.w;
        }
        *(float4*)&Ws[tid >> 4][(tid & 15) * 4] =
            *(const float4*)(W + (size_t)(kt + (tid >> 4)) * 128 + col0 + (tid & 15) * 4);
        __syncthreads();
#pragma unroll
        for (int kk = 0; kk < 16; kk++) {
            float a[8];
            float4 a0 = *(float4*)&As[kk][ty * 8];
            float4 a1 = *(float4*)&As[kk][ty * 8 + 4];
            a[0] = a0.x; a[1] = a0.y; a[2] = a0.z; a[3] = a0.w;
            a[4] = a1.x; a[5] = a1.y; a[6] = a1.z; a[7] = a1.w;
            float4 w0 = *(float4*)&Ws[kk][tx * 4];
            float wv[4] = {w0.x, w0.y, w0.z, w0.w};
#pragma unroll
            for (int r = 0; r < 8; r++)
#pragma unroll
                for (int c = 0; c < 4; c++) acc[r][c] += a[r] * wv[c];
        }
        __syncthreads();
    }
#pragma unroll
    for (int r = 0; r < 8; r++) {
        int gr = row0 + ty * 8 + r;
#pragma unroll
        for (int c = 0; c < 4; c++) {
            int gc = col0 + tx * 4 + c;
            C[(size_t)gr * 128 + gc] = acc[r][c] + bias[gc];
        }
    }
}

// ---------------- launch ----------------
extern "C" void kernel_launch(void* const* d_in, const int* in_sizes, int n_in,
                              void* d_out, int out_size)
{
    const float* features = (const float*)d_in[0];
    const float* bn0_g = (const float*)d_in[1];
    const float* bn0_b = (const float*)d_in[2];
    const float* bn0_m = (const float*)d_in[3];
    const float* bn0_v = (const float*)d_in[4];
    const float* Ws0   = (const float*)d_in[5];
    const float* Ws1   = (const float*)d_in[6];
    const float* Wu    = (const float*)d_in[7];
    const float* ft_g  = (const float*)d_in[8];
    const float* ft_b  = (const float*)d_in[9];
    const float* ft_m  = (const float*)d_in[10];
    const float* ft_v  = (const float*)d_in[11];
    const float* W_att = (const float*)d_in[12];
    const float* att_g = (const float*)d_in[13];
    const float* att_b = (const float*)d_in[14];
    const float* att_m = (const float*)d_in[15];
    const float* att_v = (const float*)d_in[16];
    const float* Wf    = (const float*)d_in[17];
    const float* bf    = (const float*)d_in[18];

    float *zp, *prior, *acc;
    fp16 *A, *h0, *h1;
    fp16 *W0, *W1, *WU, *WA;
    float *fts, *ftt, *as, *at;
    cudaGetSymbolAddress((void**)&A, g_A);
    cudaGetSymbolAddress((void**)&h0, g_h0);
    cudaGetSymbolAddress((void**)&h1, g_h1);
    cudaGetSymbolAddress((void**)&zp, g_z);
    cudaGetSymbolAddress((void**)&prior, g_prior);
    cudaGetSymbolAddress((void**)&acc, g_acc);
    cudaGetSymbolAddress((void**)&W0, g_W0);
    cudaGetSymbolAddress((void**)&W1, g_W1);
    cudaGetSymbolAddress((void**)&WU, g_WU);
    cudaGetSymbolAddress((void**)&WA, g_WA);
    cudaGetSymbolAddress((void**)&fts, g_fts);
    cudaGetSymbolAddress((void**)&ftt, g_ftt);
    cudaGetSymbolAddress((void**)&as, g_as);
    cudaGetSymbolAddress((void**)&at, g_at);

    float* outF  = (float*)d_out;
    float* masks = outF + (size_t)BATCH * OUTD;

    static bool attr_set = false;
    if (!attr_set) {
        cudaFuncSetAttribute(k_mma_s<0, 0>, cudaFuncAttributeMaxDynamicSharedMemorySize, SMEM_S);
        cudaFuncSetAttribute(k_mma_s<1, 0>, cudaFuncAttributeMaxDynamicSharedMemorySize, SMEM_S);
        cudaFuncSetAttribute(k_mma_s<1, 1>, cudaFuncAttributeMaxDynamicSharedMemorySize, SMEM_S);
        cudaFuncSetAttribute(k_mma_b, cudaFuncAttributeMaxDynamicSharedMemorySize, SMEM_B);
        attr_set = true;
    }

    // fused setup: vectorized init + tiled-transpose weight prep + bn prep
    k_setup<<<SETUP_BLK, 256>>>(features, bn0_g, bn0_b, bn0_m, bn0_v,
                                Ws0, Ws1, Wu, W_att,
                                ft_g, ft_b, ft_m, ft_v,
                                att_g, att_b, att_m, att_v);

    const dim3 gS(4, BATCH / 64);
    const dim3 gB(4, BATCH / 128);

    auto ft_transformer = [&](int t, float* accOut) {
        const float* s0 = fts + (size_t)t * 4 * 512;
        const float* t0 = ftt + (size_t)t * 4 * 512;
        k_mma_b<<<gB, 256, SMEM_B>>>(A, 512, 512, W0, s0, t0, h0);
        k_mma_s<0, 0><<<gS, 256, SMEM_S>>>(h0, 256, 256, W1,
            s0 + 512, t0 + 512, h0, h1, nullptr, nullptr, nullptr);
        k_mma_s<0, 0><<<gS, 256, SMEM_S>>>(h1, 256, 256,
            WU + (size_t)(t * 2 + 0) * 512 * 256,
            s0 + 1024, t0 + 1024, h1, h0, nullptr, nullptr, nullptr);
        k_mma_s<0, 0><<<gS, 256, SMEM_S>>>(h0, 256, 256,
            WU + (size_t)(t * 2 + 1) * 512 * 256,
            s0 + 1536, t0 + 1536, h0, h1, accOut, nullptr, nullptr);
    };

    ft_transformer(0, nullptr);

    for (int s = 0; s < STEPS; s++) {
        if (s == 0) {
            k_mma_s<1, 0><<<gS, 256, SMEM_S>>>(h1 + 128, 256, 128,
                WA, as, at, nullptr, nullptr, nullptr, nullptr, zp);
            k_sparsemax<1><<<BATCH / 8, 256>>>(zp, prior, masks, A);
        } else {
            k_mma_s<1, 1><<<gS, 256, SMEM_S>>>(h1 + 128, 256, 128,
                WA + (size_t)s * 512 * 128,
                as + (size_t)s * 512, at + (size_t)s * 512,
                nullptr, nullptr, nullptr,
                prior, zp);
            k_sparsemax<0><<<BATCH / 8, 256>>>(zp, prior,
                masks + (size_t)s * BATCH * FDIM, A);
        }
        ft_transformer(s + 1, acc);
    }

    k_fin<<<dim3(2, BATCH / 128), 256>>>(acc, Wf, bf, outF);
}